// round 11
// baseline (speedup 1.0000x reference)
#include <cuda_runtime.h>
#include <cuda_fp16.h>
#include <cstdint>

#define BATCH 4
#define SEQ   2048
#define DIM   1024
#define MQ    (BATCH * SEQ)   // 8192

// ---------------------------------------------------------------------------
// Persistent scratch (device globals — allocation-free per harness rules)
// ---------------------------------------------------------------------------
__device__ half  g_xh[(long)MQ * DIM];
__device__ half  g_Wh[3][(long)DIM * DIM];
__device__ half  g_QKV[3][(long)MQ * DIM];        // Q, K, V contiguous slices
__device__ float g_S[(long)BATCH * SEQ * SEQ];
__device__ half  g_Ph[(long)BATCH * SEQ * SEQ];

// ---------------------------------------------------------------------------
// helpers
// ---------------------------------------------------------------------------
__device__ __forceinline__ uint32_t smem_u32(const void* p) {
    uint32_t a;
    asm("{ .reg .u64 t; cvta.to.shared.u64 t, %1; cvt.u32.u64 %0, t; }" : "=r"(a) : "l"(p));
    return a;
}
__device__ __forceinline__ void cp8(uint32_t dst, const void* src) {
    asm volatile("cp.async.ca.shared.global [%0], [%1], 8;" :: "r"(dst), "l"(src));
}
__device__ __forceinline__ void cp_commit() {
    asm volatile("cp.async.commit_group;" ::: "memory");
}
__device__ __forceinline__ void cp_wait1() {
    asm volatile("cp.async.wait_group 1;" ::: "memory");
}
__device__ __forceinline__ void ldsm4(uint32_t r[4], uint32_t addr) {
    asm volatile("ldmatrix.sync.aligned.m8n8.x4.shared.b16 {%0,%1,%2,%3}, [%4];"
                 : "=r"(r[0]), "=r"(r[1]), "=r"(r[2]), "=r"(r[3]) : "r"(addr));
}
__device__ __forceinline__ void ldsm4t(uint32_t r[4], uint32_t addr) {
    asm volatile("ldmatrix.sync.aligned.m8n8.x4.trans.shared.b16 {%0,%1,%2,%3}, [%4];"
                 : "=r"(r[0]), "=r"(r[1]), "=r"(r[2]), "=r"(r[3]) : "r"(addr));
}
__device__ __forceinline__ void mma16816(float c[4], const uint32_t a[4],
                                         uint32_t b0, uint32_t b1) {
    asm volatile(
        "mma.sync.aligned.m16n8k16.row.col.f32.f16.f16.f32 "
        "{%0,%1,%2,%3}, {%4,%5,%6,%7}, {%8,%9}, {%0,%1,%2,%3};"
        : "+f"(c[0]), "+f"(c[1]), "+f"(c[2]), "+f"(c[3])
        : "r"(a[0]), "r"(a[1]), "r"(a[2]), "r"(a[3]), "r"(b0), "r"(b1));
}

// ---------------------------------------------------------------------------
// fp32 -> fp16 casts: y=0 -> x, y=1..3 -> Wq/Wk/Wv
// ---------------------------------------------------------------------------
__global__ void cast_all(const float* __restrict__ x,
                         const float* __restrict__ w0, const float* __restrict__ w1,
                         const float* __restrict__ w2,
                         half* __restrict__ xh, half* __restrict__ Wh)
{
    const int y = blockIdx.y;
    const float* s;
    half* d;
    int n4;
    if (y == 0) { s = x;  d = xh; n4 = MQ * DIM / 4; }
    else {
        s = (y == 1) ? w0 : (y == 2) ? w1 : w2;
        d = Wh + (long)(y - 1) * DIM * DIM;
        n4 = DIM * DIM / 4;
    }
    int i = blockIdx.x * blockDim.x + threadIdx.x;
    if (i >= n4) return;
    float4 v = ((const float4*)s)[i];
    half2 a; a.x = __float2half(v.x); a.y = __float2half(v.y);
    half2 b; b.x = __float2half(v.z); b.y = __float2half(v.w);
    ((half2*)d)[2 * i] = a;
    ((half2*)d)[2 * i + 1] = b;
}

// ---------------------------------------------------------------------------
// fp16 HMMA GEMM (f32 accum), cp.async 3-stage pipeline.
//   C[M,N] = A[M,K] * op(B)
//   BKMAJOR=1: B is [N,K] row-major (NT).   BKMAJOR=0: B is [K,N] row-major (NN).
//   MODE 1 (projection): z selects W slice / bias / output slice; A shared.
//          fp16 out + bias.
//   MODE 2: fp32 out * alpha; z = batch index (strides sA/sB/sC).
// CTA tile 128x128, BK=32, 8 warps (2x4), warp tile 64x32.
// ---------------------------------------------------------------------------
#define LDA    40    // elems; 80B rows (bank-conflict-free for ldmatrix)
#define LDBNN  136   // elems; 272B rows
#define STAGES 3

#define A_TILE_B   (128 * LDA * 2)          // 10240
#define BNT_TILE_B (128 * LDA * 2)          // 10240
#define BNN_TILE_B (32 * LDBNN * 2)         // 8704

template <bool BKMAJOR, int MODE>
__global__ __launch_bounds__(256)
void hmma_gemm(const half* __restrict__ A, const half* __restrict__ B,
               const float* __restrict__ b0, const float* __restrict__ b1,
               const float* __restrict__ b2,
               float* __restrict__ Cf, half* __restrict__ Ch,
               int M, int N, int K, long sA, long sB, long sC, float alpha)
{
    constexpr int B_TILE_B = BKMAJOR ? BNT_TILE_B : BNN_TILE_B;
    constexpr int OFF_B    = A_TILE_B;
    constexpr int STAGE_B  = A_TILE_B + B_TILE_B;

    extern __shared__ char smem[];
    const uint32_t sb = smem_u32(smem);

    const int tid = threadIdx.x;
    const int lane = tid & 31;
    const int wid = tid >> 5;
    const int wm = wid >> 2;        // 0..1
    const int wn = wid & 3;         // 0..3

    const int bz = blockIdx.z;
    const float* bias = b0;
    if (MODE == 1) {
        B += bz * sB;
        Ch += bz * sC;
        bias = (bz == 0) ? b0 : (bz == 1) ? b1 : b2;
    } else {
        A += bz * sA;
        B += bz * sB;
    }
    const int m0 = blockIdx.y * 128;
    const int n0 = blockIdx.x * 128;

    float c[4][4][4];
    #pragma unroll
    for (int i = 0; i < 4; i++)
        #pragma unroll
        for (int j = 0; j < 4; j++)
            #pragma unroll
            for (int r = 0; r < 4; r++) c[i][j][r] = 0.f;

    // ---- async copy of one 32-K slab into stage st ----
    auto issue_stage = [&](int st, int k0) {
        const uint32_t s0 = sb + st * STAGE_B;
        #pragma unroll
        for (int i = 0; i < 4; i++) {
            const int q = i * 256 + tid;
            const int r = q >> 3, ch = q & 7;
            cp8(s0 + r * 80 + ch * 8, A + (long)(m0 + r) * K + k0 + ch * 4);
        }
        if (BKMAJOR) {
            #pragma unroll
            for (int i = 0; i < 4; i++) {
                const int q = i * 256 + tid;
                const int r = q >> 3, ch = q & 7;
                cp8(s0 + OFF_B + r * 80 + ch * 8, B + (long)(n0 + r) * K + k0 + ch * 4);
            }
        } else {
            #pragma unroll
            for (int i = 0; i < 4; i++) {
                const int q = i * 256 + tid;
                const int r = q >> 5, ch = q & 31;
                cp8(s0 + OFF_B + r * 272 + ch * 8, B + (long)(k0 + r) * N + n0 + ch * 4);
            }
        }
        cp_commit();
    };

    const int NIT = K >> 5;
    issue_stage(0, 0);
    issue_stage(1, 32);

    int st = 0;
    for (int it = 0; it < NIT; it++) {
        cp_wait1();
        __syncthreads();
        if (it + 2 < NIT) issue_stage((st + 2) % STAGES, (it + 2) * 32);

        const half* tA = (const half*)(smem + st * STAGE_B);
        const half* tB = (const half*)(smem + st * STAGE_B + OFF_B);

        #pragma unroll
        for (int ks = 0; ks < 2; ks++) {
            const int kk = ks * 16;
            uint32_t fa[4][4], fb[2][4];
            #pragma unroll
            for (int mf = 0; mf < 4; mf++) {
                const int row = wm * 64 + mf * 16 + (lane & 15);
                const int col = kk + (lane >> 4) * 8;
                ldsm4(fa[mf], smem_u32(&tA[row * LDA + col]));
            }
            if (BKMAJOR) {
                #pragma unroll
                for (int q = 0; q < 2; q++) {
                    const int row = wn * 32 + q * 16 + (lane & 15);
                    const int col = kk + (lane >> 4) * 8;
                    ldsm4(fb[q], smem_u32(&tB[row * LDA + col]));
                }
            } else {
                #pragma unroll
                for (int q = 0; q < 2; q++) {
                    const int row = kk + (lane >> 4) * 8 + (lane & 7);
                    const int col = wn * 32 + q * 16 + ((lane >> 3) & 1) * 8;
                    ldsm4t(fb[q], smem_u32(&tB[row * LDBNN + col]));
                }
            }
            #pragma unroll
            for (int mf = 0; mf < 4; mf++)
                #pragma unroll
                for (int nf = 0; nf < 4; nf++) {
                    const int q = nf >> 1, g = nf & 1;
                    mma16816(c[mf][nf], fa[mf], fb[q][g], fb[q][g + 2]);
                }
        }
        st = (st + 1) % STAGES;
    }

    // ---- epilogue ----
    #pragma unroll
    for (int mf = 0; mf < 4; mf++) {
        const int m_lo = m0 + wm * 64 + mf * 16 + (lane >> 2);
        #pragma unroll
        for (int nf = 0; nf < 4; nf++) {
            const int n = n0 + wn * 32 + nf * 8 + (lane & 3) * 2;
            if (MODE == 1) {
                const float v0 = bias[n], v1 = bias[n + 1];
                __half2 h0; h0.x = __float2half(c[mf][nf][0] + v0);
                h0.y = __float2half(c[mf][nf][1] + v1);
                __half2 h1; h1.x = __float2half(c[mf][nf][2] + v0);
                h1.y = __float2half(c[mf][nf][3] + v1);
                *(__half2*)(Ch + (long)m_lo * N + n) = h0;
                *(__half2*)(Ch + (long)(m_lo + 8) * N + n) = h1;
            } else {
                float* co = Cf + bz * sC;
                float2 v0 = make_float2(c[mf][nf][0] * alpha, c[mf][nf][1] * alpha);
                float2 v1 = make_float2(c[mf][nf][2] * alpha, c[mf][nf][3] * alpha);
                *(float2*)(co + (long)m_lo * N + n) = v0;
                *(float2*)(co + (long)(m_lo + 8) * N + n) = v1;
            }
        }
    }
}

// ---------------------------------------------------------------------------
// Softmax over rows of g_S (len SEQ) -> fp16 probs.  Vectorized:
// float4 loads (2/thread), packed 4xhalf stores (uint2), per-row block.
// ---------------------------------------------------------------------------
__global__ __launch_bounds__(256)
void softmax_rows(const float* __restrict__ S, half* __restrict__ Ph)
{
    const float4* p4 = (const float4*)(S + (long)blockIdx.x * SEQ);
    half* ph = Ph + (long)blockIdx.x * SEQ;
    const int tid = threadIdx.x;
    __shared__ float red[8];

    float4 v0 = p4[tid];
    float4 v1 = p4[tid + 256];

    float m = fmaxf(fmaxf(fmaxf(v0.x, v0.y), fmaxf(v0.z, v0.w)),
                    fmaxf(fmaxf(v1.x, v1.y), fmaxf(v1.z, v1.w)));
    #pragma unroll
    for (int o = 16; o; o >>= 1) m = fmaxf(m, __shfl_xor_sync(0xffffffffu, m, o));
    if ((tid & 31) == 0) red[tid >> 5] = m;
    __syncthreads();
    m = red[0];
    #pragma unroll
    for (int w = 1; w < 8; w++) m = fmaxf(m, red[w]);
    __syncthreads();

    v0.x = __expf(v0.x - m); v0.y = __expf(v0.y - m);
    v0.z = __expf(v0.z - m); v0.w = __expf(v0.w - m);
    v1.x = __expf(v1.x - m); v1.y = __expf(v1.y - m);
    v1.z = __expf(v1.z - m); v1.w = __expf(v1.w - m);
    float s = (v0.x + v0.y) + (v0.z + v0.w) + (v1.x + v1.y) + (v1.z + v1.w);
    #pragma unroll
    for (int o = 16; o; o >>= 1) s += __shfl_xor_sync(0xffffffffu, s, o);
    if ((tid & 31) == 0) red[tid >> 5] = s;
    __syncthreads();
    s = 0.f;
    #pragma unroll
    for (int w = 0; w < 8; w++) s += red[w];
    const float inv = 1.f / s;

    __half2 a, b;
    uint2 pk;
    a.x = __float2half(v0.x * inv); a.y = __float2half(v0.y * inv);
    b.x = __float2half(v0.z * inv); b.y = __float2half(v0.w * inv);
    pk.x = *(uint32_t*)&a; pk.y = *(uint32_t*)&b;
    ((uint2*)ph)[tid] = pk;
    a.x = __float2half(v1.x * inv); a.y = __float2half(v1.y * inv);
    b.x = __float2half(v1.z * inv); b.y = __float2half(v1.w * inv);
    pk.x = *(uint32_t*)&a; pk.y = *(uint32_t*)&b;
    ((uint2*)ph)[tid + 256] = pk;
}

// ---------------------------------------------------------------------------
// Launch
// ---------------------------------------------------------------------------
extern "C" void kernel_launch(void* const* d_in, const int* in_sizes, int n_in,
                              void* d_out, int out_size)
{
    const float* x  = (const float*)d_in[0];
    const float* Wq = (const float*)d_in[1];
    const float* bq = (const float*)d_in[2];
    const float* Wk = (const float*)d_in[3];
    const float* bk = (const float*)d_in[4];
    const float* Wv = (const float*)d_in[5];
    const float* bv = (const float*)d_in[6];
    float* out = (float*)d_out;

    half *xh, *Wh, *QKV, *Ph;
    float* S;
    cudaGetSymbolAddress((void**)&xh, g_xh);
    cudaGetSymbolAddress((void**)&Wh, g_Wh);
    cudaGetSymbolAddress((void**)&QKV, g_QKV);
    cudaGetSymbolAddress((void**)&S, g_S);
    cudaGetSymbolAddress((void**)&Ph, g_Ph);

    half* Qh = QKV;
    half* Kh = QKV + (long)MQ * DIM;
    half* Vh = QKV + 2L * MQ * DIM;

    const int SMEM_NT = STAGES * (A_TILE_B + BNT_TILE_B);   // 61440
    const int SMEM_NN = STAGES * (A_TILE_B + BNN_TILE_B);   // 56832
    cudaFuncSetAttribute(hmma_gemm<true, 1>, cudaFuncAttributeMaxDynamicSharedMemorySize, SMEM_NT);
    cudaFuncSetAttribute(hmma_gemm<true, 2>, cudaFuncAttributeMaxDynamicSharedMemorySize, SMEM_NT);
    cudaFuncSetAttribute(hmma_gemm<false, 2>, cudaFuncAttributeMaxDynamicSharedMemorySize, SMEM_NN);

    const long WSZ = (long)DIM * DIM;

    // 1) casts: x + all three W in one launch
    {
        dim3 grid((MQ * DIM / 4 + 255) / 256, 4, 1);
        cast_all<<<grid, 256>>>(x, Wq, Wk, Wv, xh, Wh);
    }

    // 2) projections: ONE launch, grid.z selects Q/K/V   (NT, fp16 out)
    {
        dim3 grid(DIM / 128, MQ / 128, 3), blk(256);
        hmma_gemm<true, 1><<<grid, blk, SMEM_NT>>>(xh, Wh, bq, bk, bv,
                                                   nullptr, QKV, MQ, DIM, DIM,
                                                   0, WSZ, (long)MQ * DIM, 1.f);
    }

    // 3) scores: S = (1/32) Q K^T  per batch  (NT, fp32 out)
    {
        dim3 grid(SEQ / 128, SEQ / 128, BATCH), blk(256);
        hmma_gemm<true, 2><<<grid, blk, SMEM_NT>>>(Qh, Kh, nullptr, nullptr, nullptr,
                                                   S, nullptr, SEQ, SEQ, DIM,
                                                   (long)SEQ * DIM, (long)SEQ * DIM, (long)SEQ * SEQ,
                                                   0.03125f);
    }

    // 4) softmax -> P fp16
    softmax_rows<<<BATCH * SEQ, 256>>>(S, Ph);

    // 5) out = P @ V  per batch  (NN via ldmatrix.trans, fp32 out)
    {
        dim3 grid(DIM / 128, SEQ / 128, BATCH), blk(256);
        hmma_gemm<false, 2><<<grid, blk, SMEM_NN>>>(Ph, Vh, nullptr, nullptr, nullptr,
                                                    out, nullptr, SEQ, DIM, SEQ,
                                                    (long)SEQ * SEQ, (long)SEQ * DIM, (long)SEQ * DIM,
                                                    1.f);
    }
}

// round 12
// speedup vs baseline: 1.0028x; 1.0028x over previous
#include <cuda_runtime.h>
#include <cuda_fp16.h>
#include <cstdint>

#define BATCH 4
#define SEQ   2048
#define DIM   1024
#define MQ    (BATCH * SEQ)   // 8192

// ---------------------------------------------------------------------------
// Persistent scratch (device globals — allocation-free per harness rules)
// ---------------------------------------------------------------------------
__device__ half  g_xh[(long)MQ * DIM];
__device__ half  g_Wh[3][(long)DIM * DIM];
__device__ half  g_QKV[3][(long)MQ * DIM];        // Q, K, V contiguous slices
__device__ float g_S[(long)BATCH * SEQ * SEQ];
__device__ half  g_Ph[(long)BATCH * SEQ * SEQ];

// ---------------------------------------------------------------------------
// helpers
// ---------------------------------------------------------------------------
__device__ __forceinline__ uint32_t smem_u32(const void* p) {
    uint32_t a;
    asm("{ .reg .u64 t; cvta.to.shared.u64 t, %1; cvt.u32.u64 %0, t; }" : "=r"(a) : "l"(p));
    return a;
}
__device__ __forceinline__ void cp8(uint32_t dst, const void* src) {
    asm volatile("cp.async.ca.shared.global [%0], [%1], 8;" :: "r"(dst), "l"(src));
}
__device__ __forceinline__ void cp_commit() {
    asm volatile("cp.async.commit_group;" ::: "memory");
}
__device__ __forceinline__ void cp_wait1() {
    asm volatile("cp.async.wait_group 1;" ::: "memory");
}
__device__ __forceinline__ void ldsm4(uint32_t r[4], uint32_t addr) {
    asm volatile("ldmatrix.sync.aligned.m8n8.x4.shared.b16 {%0,%1,%2,%3}, [%4];"
                 : "=r"(r[0]), "=r"(r[1]), "=r"(r[2]), "=r"(r[3]) : "r"(addr));
}
__device__ __forceinline__ void ldsm4t(uint32_t r[4], uint32_t addr) {
    asm volatile("ldmatrix.sync.aligned.m8n8.x4.trans.shared.b16 {%0,%1,%2,%3}, [%4];"
                 : "=r"(r[0]), "=r"(r[1]), "=r"(r[2]), "=r"(r[3]) : "r"(addr));
}
__device__ __forceinline__ void mma16816(float c[4], const uint32_t a[4],
                                         uint32_t b0, uint32_t b1) {
    asm volatile(
        "mma.sync.aligned.m16n8k16.row.col.f32.f16.f16.f32 "
        "{%0,%1,%2,%3}, {%4,%5,%6,%7}, {%8,%9}, {%0,%1,%2,%3};"
        : "+f"(c[0]), "+f"(c[1]), "+f"(c[2]), "+f"(c[3])
        : "r"(a[0]), "r"(a[1]), "r"(a[2]), "r"(a[3]), "r"(b0), "r"(b1));
}

// ---------------------------------------------------------------------------
// fp32 -> fp16 casts: y=0 -> x, y=1..3 -> Wq/Wk/Wv
// ---------------------------------------------------------------------------
__global__ void cast_all(const float* __restrict__ x,
                         const float* __restrict__ w0, const float* __restrict__ w1,
                         const float* __restrict__ w2,
                         half* __restrict__ xh, half* __restrict__ Wh)
{
    const int y = blockIdx.y;
    const float* s;
    half* d;
    int n4;
    if (y == 0) { s = x;  d = xh; n4 = MQ * DIM / 4; }
    else {
        s = (y == 1) ? w0 : (y == 2) ? w1 : w2;
        d = Wh + (long)(y - 1) * DIM * DIM;
        n4 = DIM * DIM / 4;
    }
    int i = blockIdx.x * blockDim.x + threadIdx.x;
    if (i >= n4) return;
    float4 v = ((const float4*)s)[i];
    half2 a; a.x = __float2half(v.x); a.y = __float2half(v.y);
    half2 b; b.x = __float2half(v.z); b.y = __float2half(v.w);
    ((half2*)d)[2 * i] = a;
    ((half2*)d)[2 * i + 1] = b;
}

// ---------------------------------------------------------------------------
// fp16 HMMA GEMM (f32 accum), cp.async 3-stage pipeline.
//   C[M,N] = A[M,K] * op(B)
//   BKMAJOR=1: B is [N,K] row-major (NT).   BKMAJOR=0: B is [K,N] row-major (NN).
//   MODE 1 (projection): z selects W slice / bias / output slice; A shared.
//          fp16 out + bias.
//   MODE 2: fp32 out * alpha; z = batch index (strides sA/sB/sC).
// CTA tile 128x128, BK=32, 8 warps (2x4), warp tile 64x32.
// ---------------------------------------------------------------------------
#define LDA    40    // elems; 80B rows (bank-conflict-free for ldmatrix)
#define LDBNN  136   // elems; 272B rows
#define STAGES 3

#define A_TILE_B   (128 * LDA * 2)          // 10240
#define BNT_TILE_B (128 * LDA * 2)          // 10240
#define BNN_TILE_B (32 * LDBNN * 2)         // 8704

template <bool BKMAJOR, int MODE>
__global__ __launch_bounds__(256)
void hmma_gemm(const half* __restrict__ A, const half* __restrict__ B,
               const float* __restrict__ b0, const float* __restrict__ b1,
               const float* __restrict__ b2,
               float* __restrict__ Cf, half* __restrict__ Ch,
               int M, int N, int K, long sA, long sB, long sC, float alpha)
{
    constexpr int B_TILE_B = BKMAJOR ? BNT_TILE_B : BNN_TILE_B;
    constexpr int OFF_B    = A_TILE_B;
    constexpr int STAGE_B  = A_TILE_B + B_TILE_B;

    extern __shared__ char smem[];
    const uint32_t sb = smem_u32(smem);

    const int tid = threadIdx.x;
    const int lane = tid & 31;
    const int wid = tid >> 5;
    const int wm = wid >> 2;        // 0..1
    const int wn = wid & 3;         // 0..3

    const int bz = blockIdx.z;
    const float* bias = b0;
    if (MODE == 1) {
        B += bz * sB;
        Ch += bz * sC;
        bias = (bz == 0) ? b0 : (bz == 1) ? b1 : b2;
    } else {
        A += bz * sA;
        B += bz * sB;
    }
    const int m0 = blockIdx.y * 128;
    const int n0 = blockIdx.x * 128;

    float c[4][4][4];
    #pragma unroll
    for (int i = 0; i < 4; i++)
        #pragma unroll
        for (int j = 0; j < 4; j++)
            #pragma unroll
            for (int r = 0; r < 4; r++) c[i][j][r] = 0.f;

    // ---- async copy of one 32-K slab into stage st ----
    auto issue_stage = [&](int st, int k0) {
        const uint32_t s0 = sb + st * STAGE_B;
        #pragma unroll
        for (int i = 0; i < 4; i++) {
            const int q = i * 256 + tid;
            const int r = q >> 3, ch = q & 7;
            cp8(s0 + r * 80 + ch * 8, A + (long)(m0 + r) * K + k0 + ch * 4);
        }
        if (BKMAJOR) {
            #pragma unroll
            for (int i = 0; i < 4; i++) {
                const int q = i * 256 + tid;
                const int r = q >> 3, ch = q & 7;
                cp8(s0 + OFF_B + r * 80 + ch * 8, B + (long)(n0 + r) * K + k0 + ch * 4);
            }
        } else {
            #pragma unroll
            for (int i = 0; i < 4; i++) {
                const int q = i * 256 + tid;
                const int r = q >> 5, ch = q & 31;
                cp8(s0 + OFF_B + r * 272 + ch * 8, B + (long)(k0 + r) * N + n0 + ch * 4);
            }
        }
        cp_commit();
    };

    const int NIT = K >> 5;
    issue_stage(0, 0);
    issue_stage(1, 32);

    int st = 0;
    for (int it = 0; it < NIT; it++) {
        cp_wait1();
        __syncthreads();
        if (it + 2 < NIT) issue_stage((st + 2) % STAGES, (it + 2) * 32);

        const half* tA = (const half*)(smem + st * STAGE_B);
        const half* tB = (const half*)(smem + st * STAGE_B + OFF_B);

        #pragma unroll
        for (int ks = 0; ks < 2; ks++) {
            const int kk = ks * 16;
            uint32_t fa[4][4], fb[2][4];
            #pragma unroll
            for (int mf = 0; mf < 4; mf++) {
                const int row = wm * 64 + mf * 16 + (lane & 15);
                const int col = kk + (lane >> 4) * 8;
                ldsm4(fa[mf], smem_u32(&tA[row * LDA + col]));
            }
            if (BKMAJOR) {
                #pragma unroll
                for (int q = 0; q < 2; q++) {
                    const int row = wn * 32 + q * 16 + (lane & 15);
                    const int col = kk + (lane >> 4) * 8;
                    ldsm4(fb[q], smem_u32(&tB[row * LDA + col]));
                }
            } else {
                #pragma unroll
                for (int q = 0; q < 2; q++) {
                    const int row = kk + (lane >> 4) * 8 + (lane & 7);
                    const int col = wn * 32 + q * 16 + ((lane >> 3) & 1) * 8;
                    ldsm4t(fb[q], smem_u32(&tB[row * LDBNN + col]));
                }
            }
            #pragma unroll
            for (int mf = 0; mf < 4; mf++)
                #pragma unroll
                for (int nf = 0; nf < 4; nf++) {
                    const int q = nf >> 1, g = nf & 1;
                    mma16816(c[mf][nf], fa[mf], fb[q][g], fb[q][g + 2]);
                }
        }
        st = (st + 1) % STAGES;
    }

    // ---- epilogue ----
    #pragma unroll
    for (int mf = 0; mf < 4; mf++) {
        const int m_lo = m0 + wm * 64 + mf * 16 + (lane >> 2);
        #pragma unroll
        for (int nf = 0; nf < 4; nf++) {
            const int n = n0 + wn * 32 + nf * 8 + (lane & 3) * 2;
            if (MODE == 1) {
                const float v0 = bias[n], v1 = bias[n + 1];
                __half2 h0; h0.x = __float2half(c[mf][nf][0] + v0);
                h0.y = __float2half(c[mf][nf][1] + v1);
                __half2 h1; h1.x = __float2half(c[mf][nf][2] + v0);
                h1.y = __float2half(c[mf][nf][3] + v1);
                *(__half2*)(Ch + (long)m_lo * N + n) = h0;
                *(__half2*)(Ch + (long)(m_lo + 8) * N + n) = h1;
            } else {
                float* co = Cf + bz * sC;
                float2 v0 = make_float2(c[mf][nf][0] * alpha, c[mf][nf][1] * alpha);
                float2 v1 = make_float2(c[mf][nf][2] * alpha, c[mf][nf][3] * alpha);
                *(float2*)(co + (long)m_lo * N + n) = v0;
                *(float2*)(co + (long)(m_lo + 8) * N + n) = v1;
            }
        }
    }
}

// ---------------------------------------------------------------------------
// Softmax over rows of g_S (len SEQ) -> fp16 probs.  Vectorized:
// float4 loads (2/thread), packed 4xhalf stores (uint2), per-row block.
// ---------------------------------------------------------------------------
__global__ __launch_bounds__(256)
void softmax_rows(const float* __restrict__ S, half* __restrict__ Ph)
{
    const float4* p4 = (const float4*)(S + (long)blockIdx.x * SEQ);
    half* ph = Ph + (long)blockIdx.x * SEQ;
    const int tid = threadIdx.x;
    __shared__ float red[8];

    float4 v0 = p4[tid];
    float4 v1 = p4[tid + 256];

    float m = fmaxf(fmaxf(fmaxf(v0.x, v0.y), fmaxf(v0.z, v0.w)),
                    fmaxf(fmaxf(v1.x, v1.y), fmaxf(v1.z, v1.w)));
    #pragma unroll
    for (int o = 16; o; o >>= 1) m = fmaxf(m, __shfl_xor_sync(0xffffffffu, m, o));
    if ((tid & 31) == 0) red[tid >> 5] = m;
    __syncthreads();
    m = red[0];
    #pragma unroll
    for (int w = 1; w < 8; w++) m = fmaxf(m, red[w]);
    __syncthreads();

    v0.x = __expf(v0.x - m); v0.y = __expf(v0.y - m);
    v0.z = __expf(v0.z - m); v0.w = __expf(v0.w - m);
    v1.x = __expf(v1.x - m); v1.y = __expf(v1.y - m);
    v1.z = __expf(v1.z - m); v1.w = __expf(v1.w - m);
    float s = (v0.x + v0.y) + (v0.z + v0.w) + (v1.x + v1.y) + (v1.z + v1.w);
    #pragma unroll
    for (int o = 16; o; o >>= 1) s += __shfl_xor_sync(0xffffffffu, s, o);
    if ((tid & 31) == 0) red[tid >> 5] = s;
    __syncthreads();
    s = 0.f;
    #pragma unroll
    for (int w = 0; w < 8; w++) s += red[w];
    const float inv = 1.f / s;

    __half2 a, b;
    uint2 pk;
    a.x = __float2half(v0.x * inv); a.y = __float2half(v0.y * inv);
    b.x = __float2half(v0.z * inv); b.y = __float2half(v0.w * inv);
    pk.x = *(uint32_t*)&a; pk.y = *(uint32_t*)&b;
    ((uint2*)ph)[tid] = pk;
    a.x = __float2half(v1.x * inv); a.y = __float2half(v1.y * inv);
    b.x = __float2half(v1.z * inv); b.y = __float2half(v1.w * inv);
    pk.x = *(uint32_t*)&a; pk.y = *(uint32_t*)&b;
    ((uint2*)ph)[tid + 256] = pk;
}

// ---------------------------------------------------------------------------
// Launch
// ---------------------------------------------------------------------------
extern "C" void kernel_launch(void* const* d_in, const int* in_sizes, int n_in,
                              void* d_out, int out_size)
{
    const float* x  = (const float*)d_in[0];
    const float* Wq = (const float*)d_in[1];
    const float* bq = (const float*)d_in[2];
    const float* Wk = (const float*)d_in[3];
    const float* bk = (const float*)d_in[4];
    const float* Wv = (const float*)d_in[5];
    const float* bv = (const float*)d_in[6];
    float* out = (float*)d_out;

    half *xh, *Wh, *QKV, *Ph;
    float* S;
    cudaGetSymbolAddress((void**)&xh, g_xh);
    cudaGetSymbolAddress((void**)&Wh, g_Wh);
    cudaGetSymbolAddress((void**)&QKV, g_QKV);
    cudaGetSymbolAddress((void**)&S, g_S);
    cudaGetSymbolAddress((void**)&Ph, g_Ph);

    half* Qh = QKV;
    half* Kh = QKV + (long)MQ * DIM;
    half* Vh = QKV + 2L * MQ * DIM;

    const int SMEM_NT = STAGES * (A_TILE_B + BNT_TILE_B);   // 61440
    const int SMEM_NN = STAGES * (A_TILE_B + BNN_TILE_B);   // 56832
    cudaFuncSetAttribute(hmma_gemm<true, 1>, cudaFuncAttributeMaxDynamicSharedMemorySize, SMEM_NT);
    cudaFuncSetAttribute(hmma_gemm<true, 2>, cudaFuncAttributeMaxDynamicSharedMemorySize, SMEM_NT);
    cudaFuncSetAttribute(hmma_gemm<false, 2>, cudaFuncAttributeMaxDynamicSharedMemorySize, SMEM_NN);

    const long WSZ = (long)DIM * DIM;

    // 1) casts: x + all three W in one launch
    {
        dim3 grid((MQ * DIM / 4 + 255) / 256, 4, 1);
        cast_all<<<grid, 256>>>(x, Wq, Wk, Wv, xh, Wh);
    }

    // 2) projections: ONE launch, grid.z selects Q/K/V   (NT, fp16 out)
    {
        dim3 grid(DIM / 128, MQ / 128, 3), blk(256);
        hmma_gemm<true, 1><<<grid, blk, SMEM_NT>>>(xh, Wh, bq, bk, bv,
                                                   nullptr, QKV, MQ, DIM, DIM,
                                                   0, WSZ, (long)MQ * DIM, 1.f);
    }

    // 3) scores: S = (1/32) Q K^T  per batch  (NT, fp32 out)
    {
        dim3 grid(SEQ / 128, SEQ / 128, BATCH), blk(256);
        hmma_gemm<true, 2><<<grid, blk, SMEM_NT>>>(Qh, Kh, nullptr, nullptr, nullptr,
                                                   S, nullptr, SEQ, SEQ, DIM,
                                                   (long)SEQ * DIM, (long)SEQ * DIM, (long)SEQ * SEQ,
                                                   0.03125f);
    }

    // 4) softmax -> P fp16
    softmax_rows<<<BATCH * SEQ, 256>>>(S, Ph);

    // 5) out = P @ V  per batch  (NN via ldmatrix.trans, fp32 out)
    {
        dim3 grid(DIM / 128, SEQ / 128, BATCH), blk(256);
        hmma_gemm<false, 2><<<grid, blk, SMEM_NN>>>(Ph, Vh, nullptr, nullptr, nullptr,
                                                    out, nullptr, SEQ, DIM, SEQ,
                                                    (long)SEQ * SEQ, (long)SEQ * DIM, (long)SEQ * DIM,
                                                    1.f);
    }
}

// round 13
// speedup vs baseline: 1.0192x; 1.0164x over previous
#include <cuda_runtime.h>
#include <cuda_fp16.h>
#include <cstdint>

#define BATCH 4
#define SEQ   2048
#define DIM   1024
#define MQ    (BATCH * SEQ)   // 8192

// ---------------------------------------------------------------------------
// Persistent scratch (device globals — allocation-free per harness rules)
// ---------------------------------------------------------------------------
__device__ half  g_xh[(long)MQ * DIM];
__device__ half  g_Wh[3][(long)DIM * DIM];
__device__ half  g_QKV[3][(long)MQ * DIM];
__device__ float g_S[(long)BATCH * SEQ * SEQ];
__device__ half  g_Ph[(long)BATCH * SEQ * SEQ];
__device__ unsigned g_qnext, g_done_qk, g_done_sc, g_done_sm;

// Tile-queue layout (dependency order):
//   [0,512)      Q-proj tiles      (tile: n 8 x m 64)
//   [512,1024)   K-proj tiles
//   [1024,1536)  V-proj tiles      (not gating scores)
//   [1536,2560)  scores tiles      gate: done_qk == 1024
//   [2560,3584)  softmax items (8 rows each)   gate: done_sc == 1024
//   [3584,4096)  AV tiles          gate: done_sm == 1024
#define T_PROJ_END 1536
#define T_SC_END   2560
#define T_SM_END   3584
#define T_TOTAL    4096

// ---------------------------------------------------------------------------
// helpers
// ---------------------------------------------------------------------------
__device__ __forceinline__ uint32_t smem_u32(const void* p) {
    uint32_t a;
    asm("{ .reg .u64 t; cvta.to.shared.u64 t, %1; cvt.u32.u64 %0, t; }" : "=r"(a) : "l"(p));
    return a;
}
__device__ __forceinline__ void cp8(uint32_t dst, const void* src) {
    asm volatile("cp.async.ca.shared.global [%0], [%1], 8;" :: "r"(dst), "l"(src));
}
__device__ __forceinline__ void cp_commit() {
    asm volatile("cp.async.commit_group;" ::: "memory");
}
__device__ __forceinline__ void cp_wait1() {
    asm volatile("cp.async.wait_group 1;" ::: "memory");
}
__device__ __forceinline__ void cp_wait0() {
    asm volatile("cp.async.wait_group 0;" ::: "memory");
}
__device__ __forceinline__ void ldsm4(uint32_t r[4], uint32_t addr) {
    asm volatile("ldmatrix.sync.aligned.m8n8.x4.shared.b16 {%0,%1,%2,%3}, [%4];"
                 : "=r"(r[0]), "=r"(r[1]), "=r"(r[2]), "=r"(r[3]) : "r"(addr));
}
__device__ __forceinline__ void ldsm4t(uint32_t r[4], uint32_t addr) {
    asm volatile("ldmatrix.sync.aligned.m8n8.x4.trans.shared.b16 {%0,%1,%2,%3}, [%4];"
                 : "=r"(r[0]), "=r"(r[1]), "=r"(r[2]), "=r"(r[3]) : "r"(addr));
}
__device__ __forceinline__ void mma16816(float c[4], const uint32_t a[4],
                                         uint32_t b0, uint32_t b1) {
    asm volatile(
        "mma.sync.aligned.m16n8k16.row.col.f32.f16.f16.f32 "
        "{%0,%1,%2,%3}, {%4,%5,%6,%7}, {%8,%9}, {%0,%1,%2,%3};"
        : "+f"(c[0]), "+f"(c[1]), "+f"(c[2]), "+f"(c[3])
        : "r"(a[0]), "r"(a[1]), "r"(a[2]), "r"(a[3]), "r"(b0), "r"(b1));
}
__device__ __forceinline__ unsigned ld_acq(const unsigned* p) {
    unsigned v;
    asm volatile("ld.acquire.gpu.u32 %0, [%1];" : "=r"(v) : "l"(p) : "memory");
    return v;
}
__device__ __forceinline__ void spin_ge(const unsigned* p, unsigned tgt) {
    int it = 0;
    while (ld_acq(p) < tgt) {
        __nanosleep(128);
        if (++it > 8000000) break;   // safety valve: fail, don't hang
    }
}

// ---------------------------------------------------------------------------
// fp32 -> fp16 casts (y=0 -> x, y=1..3 -> W) + sync-counter reset
// ---------------------------------------------------------------------------
__global__ void cast_all(const float* __restrict__ x,
                         const float* __restrict__ w0, const float* __restrict__ w1,
                         const float* __restrict__ w2,
                         half* __restrict__ xh, half* __restrict__ Wh)
{
    if (blockIdx.x == 0 && blockIdx.y == 0 && threadIdx.x == 0) {
        g_qnext = 0; g_done_qk = 0; g_done_sc = 0; g_done_sm = 0;
    }
    const int y = blockIdx.y;
    const float* s;
    half* d;
    int n4;
    if (y == 0) { s = x;  d = xh; n4 = MQ * DIM / 4; }
    else {
        s = (y == 1) ? w0 : (y == 2) ? w1 : w2;
        d = Wh + (long)(y - 1) * DIM * DIM;
        n4 = DIM * DIM / 4;
    }
    int i = blockIdx.x * blockDim.x + threadIdx.x;
    if (i >= n4) return;
    float4 v = ((const float4*)s)[i];
    half2 a; a.x = __float2half(v.x); a.y = __float2half(v.y);
    half2 b; b.x = __float2half(v.z); b.y = __float2half(v.w);
    ((half2*)d)[2 * i] = a;
    ((half2*)d)[2 * i + 1] = b;
}

// ---------------------------------------------------------------------------
// GEMM tile body (same proven math as the 510us build).
//   C[128,128] @ (m0,n0) = A[M,K] * op(B)   fp16 in, f32 accum
//   BKMAJOR=1: B [N,K] (NT).   BKMAJOR=0: B [K,N] (NN).
//   MODE 1: fp16 out + bias.   MODE 2: fp32 out * alpha.
// ---------------------------------------------------------------------------
#define LDA    40
#define LDBNN  136
#define STAGES 3

#define A_TILE_B   (128 * LDA * 2)          // 10240
#define BNT_TILE_B (128 * LDA * 2)          // 10240
#define BNN_TILE_B (32 * LDBNN * 2)         // 8704
#define SMEM_MEGA  (STAGES * (A_TILE_B + BNT_TILE_B))   // 61440 (NT >= NN)

template <bool BKMAJOR, int MODE>
__device__ __forceinline__ void gemm_body(
    char* smem,
    const half* __restrict__ A, const half* __restrict__ B,
    const float* __restrict__ bias,
    float* __restrict__ Cf, half* __restrict__ Ch,
    int N, int K, int m0, int n0, float alpha)
{
    constexpr int B_TILE_B = BKMAJOR ? BNT_TILE_B : BNN_TILE_B;
    constexpr int OFF_B    = A_TILE_B;
    constexpr int STAGE_B  = A_TILE_B + B_TILE_B;

    const uint32_t sb = smem_u32(smem);
    const int tid = threadIdx.x;
    const int lane = tid & 31;
    const int wid = tid >> 5;
    const int wm = wid >> 2;
    const int wn = wid & 3;

    float c[4][4][4];
    #pragma unroll
    for (int i = 0; i < 4; i++)
        #pragma unroll
        for (int j = 0; j < 4; j++)
            #pragma unroll
            for (int r = 0; r < 4; r++) c[i][j][r] = 0.f;

    auto issue_stage = [&](int st, int k0) {
        const uint32_t s0 = sb + st * STAGE_B;
        #pragma unroll
        for (int i = 0; i < 4; i++) {
            const int q = i * 256 + tid;
            const int r = q >> 3, ch = q & 7;
            cp8(s0 + r * 80 + ch * 8, A + (long)(m0 + r) * K + k0 + ch * 4);
        }
        if (BKMAJOR) {
            #pragma unroll
            for (int i = 0; i < 4; i++) {
                const int q = i * 256 + tid;
                const int r = q >> 3, ch = q & 7;
                cp8(s0 + OFF_B + r * 80 + ch * 8, B + (long)(n0 + r) * K + k0 + ch * 4);
            }
        } else {
            #pragma unroll
            for (int i = 0; i < 4; i++) {
                const int q = i * 256 + tid;
                const int r = q >> 5, ch = q & 31;
                cp8(s0 + OFF_B + r * 272 + ch * 8, B + (long)(k0 + r) * N + n0 + ch * 4);
            }
        }
        cp_commit();
    };

    const int NIT = K >> 5;
    issue_stage(0, 0);
    issue_stage(1, 32);

    int st = 0;
    for (int it = 0; it < NIT; it++) {
        cp_wait1();
        __syncthreads();
        if (it + 2 < NIT) issue_stage((st + 2) % STAGES, (it + 2) * 32);

        const half* tA = (const half*)(smem + st * STAGE_B);
        const half* tB = (const half*)(smem + st * STAGE_B + OFF_B);

        #pragma unroll
        for (int ks = 0; ks < 2; ks++) {
            const int kk = ks * 16;
            uint32_t fa[4][4], fb[2][4];
            #pragma unroll
            for (int mf = 0; mf < 4; mf++) {
                const int row = wm * 64 + mf * 16 + (lane & 15);
                const int col = kk + (lane >> 4) * 8;
                ldsm4(fa[mf], smem_u32(&tA[row * LDA + col]));
            }
            if (BKMAJOR) {
                #pragma unroll
                for (int q = 0; q < 2; q++) {
                    const int row = wn * 32 + q * 16 + (lane & 15);
                    const int col = kk + (lane >> 4) * 8;
                    ldsm4(fb[q], smem_u32(&tB[row * LDA + col]));
                }
            } else {
                #pragma unroll
                for (int q = 0; q < 2; q++) {
                    const int row = kk + (lane >> 4) * 8 + (lane & 7);
                    const int col = wn * 32 + q * 16 + ((lane >> 3) & 1) * 8;
                    ldsm4t(fb[q], smem_u32(&tB[row * LDBNN + col]));
                }
            }
            #pragma unroll
            for (int mf = 0; mf < 4; mf++)
                #pragma unroll
                for (int nf = 0; nf < 4; nf++) {
                    const int q = nf >> 1, g = nf & 1;
                    mma16816(c[mf][nf], fa[mf], fb[q][g], fb[q][g + 2]);
                }
        }
        st = (st + 1) % STAGES;
    }
    cp_wait0();   // drain outstanding cp.async before smem reuse by next tile

    #pragma unroll
    for (int mf = 0; mf < 4; mf++) {
        const int m_lo = m0 + wm * 64 + mf * 16 + (lane >> 2);
        #pragma unroll
        for (int nf = 0; nf < 4; nf++) {
            const int n = n0 + wn * 32 + nf * 8 + (lane & 3) * 2;
            if (MODE == 1) {
                const float v0 = bias[n], v1 = bias[n + 1];
                __half2 h0; h0.x = __float2half(c[mf][nf][0] + v0);
                h0.y = __float2half(c[mf][nf][1] + v1);
                __half2 h1; h1.x = __float2half(c[mf][nf][2] + v0);
                h1.y = __float2half(c[mf][nf][3] + v1);
                *(__half2*)(Ch + (long)m_lo * N + n) = h0;
                *(__half2*)(Ch + (long)(m_lo + 8) * N + n) = h1;
            } else {
                float2 v0 = make_float2(c[mf][nf][0] * alpha, c[mf][nf][1] * alpha);
                float2 v1 = make_float2(c[mf][nf][2] * alpha, c[mf][nf][3] * alpha);
                *(float2*)(Cf + (long)m_lo * N + n) = v0;
                *(float2*)(Cf + (long)(m_lo + 8) * N + n) = v1;
            }
        }
    }
}

// ---------------------------------------------------------------------------
// One softmax row (vectorized), smem red[] at base of dynamic smem
// ---------------------------------------------------------------------------
__device__ __forceinline__ void softmax_row(char* smem, long row)
{
    float* red = (float*)smem;
    const float4* p4 = (const float4*)(g_S + row * SEQ);
    half* ph = g_Ph + row * SEQ;
    const int tid = threadIdx.x;

    float4 v0 = p4[tid];
    float4 v1 = p4[tid + 256];

    float m = fmaxf(fmaxf(fmaxf(v0.x, v0.y), fmaxf(v0.z, v0.w)),
                    fmaxf(fmaxf(v1.x, v1.y), fmaxf(v1.z, v1.w)));
    #pragma unroll
    for (int o = 16; o; o >>= 1) m = fmaxf(m, __shfl_xor_sync(0xffffffffu, m, o));
    if ((tid & 31) == 0) red[tid >> 5] = m;
    __syncthreads();
    m = red[0];
    #pragma unroll
    for (int w = 1; w < 8; w++) m = fmaxf(m, red[w]);
    __syncthreads();

    v0.x = __expf(v0.x - m); v0.y = __expf(v0.y - m);
    v0.z = __expf(v0.z - m); v0.w = __expf(v0.w - m);
    v1.x = __expf(v1.x - m); v1.y = __expf(v1.y - m);
    v1.z = __expf(v1.z - m); v1.w = __expf(v1.w - m);
    float s = (v0.x + v0.y) + (v0.z + v0.w) + (v1.x + v1.y) + (v1.z + v1.w);
    #pragma unroll
    for (int o = 16; o; o >>= 1) s += __shfl_xor_sync(0xffffffffu, s, o);
    if ((tid & 31) == 0) red[tid >> 5] = s;
    __syncthreads();
    s = 0.f;
    #pragma unroll
    for (int w = 0; w < 8; w++) s += red[w];
    const float inv = 1.f / s;

    __half2 a, b;
    uint2 pk;
    a.x = __float2half(v0.x * inv); a.y = __float2half(v0.y * inv);
    b.x = __float2half(v0.z * inv); b.y = __float2half(v0.w * inv);
    pk.x = *(uint32_t*)&a; pk.y = *(uint32_t*)&b;
    ((uint2*)ph)[tid] = pk;
    a.x = __float2half(v1.x * inv); a.y = __float2half(v1.y * inv);
    b.x = __float2half(v1.z * inv); b.y = __float2half(v1.w * inv);
    pk.x = *(uint32_t*)&a; pk.y = *(uint32_t*)&b;
    ((uint2*)ph)[tid + 256] = pk;
    __syncthreads();
}

// ---------------------------------------------------------------------------
// Persistent mega-kernel: atomic tile queue over all phases
// ---------------------------------------------------------------------------
__global__ __launch_bounds__(256, 2)
void mega(const float* __restrict__ bq, const float* __restrict__ bk,
          const float* __restrict__ bv, float* __restrict__ out)
{
    extern __shared__ char smem[];
    __shared__ unsigned s_t;
    const int tid = threadIdx.x;

    for (;;) {
        if (tid == 0) s_t = atomicAdd(&g_qnext, 1u);
        __syncthreads();
        const unsigned t = s_t;
        if (t >= T_TOTAL) return;

        if (t < T_PROJ_END) {
            // ---- projections: Q(0..511), K(512..1023), V(1024..1535) ----
            const int zsel = t >> 9;
            const int tt = t & 511;
            const int n0 = (tt & 7) * 128;
            const int m0 = (tt >> 3) * 128;
            const float* bias = (zsel == 0) ? bq : (zsel == 1) ? bk : bv;
            gemm_body<true, 1>(smem, g_xh, g_Wh[zsel], bias,
                               nullptr, g_QKV[zsel], DIM, DIM, m0, n0, 1.f);
            if (t < 1024) {
                __threadfence();
                __syncthreads();
                if (tid == 0) atomicAdd(&g_done_qk, 1u);
            }
        } else if (t < T_SC_END) {
            // ---- scores: S = (1/32) Q K^T ----
            if (tid == 0) spin_ge(&g_done_qk, 1024u);
            __syncthreads();
            const int tt = t - T_PROJ_END;
            const int bz = tt >> 8;
            const int r = tt & 255;
            const int n0 = (r & 15) * 128;
            const int m0 = (r >> 4) * 128;
            gemm_body<true, 2>(smem,
                               g_QKV[0] + (long)bz * SEQ * DIM,
                               g_QKV[1] + (long)bz * SEQ * DIM, nullptr,
                               g_S + (long)bz * SEQ * SEQ, nullptr,
                               SEQ, DIM, m0, n0, 0.03125f);
            __threadfence();
            __syncthreads();
            if (tid == 0) atomicAdd(&g_done_sc, 1u);
        } else if (t < T_SM_END) {
            // ---- softmax: 8 rows per item ----
            if (tid == 0) spin_ge(&g_done_sc, 1024u);
            __syncthreads();
            const long base = (long)(t - T_SC_END) * 8;
            #pragma unroll 1
            for (int i = 0; i < 8; i++) softmax_row(smem, base + i);
            __threadfence();
            __syncthreads();
            if (tid == 0) atomicAdd(&g_done_sm, 1u);
        } else {
            // ---- AV: out = P @ V ----
            if (tid == 0) spin_ge(&g_done_sm, 1024u);
            __syncthreads();
            const int tt = t - T_SM_END;
            const int bz = tt >> 7;
            const int r = tt & 127;
            const int n0 = (r & 7) * 128;
            const int m0 = (r >> 3) * 128;
            gemm_body<false, 2>(smem,
                                g_Ph + (long)bz * SEQ * SEQ,
                                g_QKV[2] + (long)bz * SEQ * DIM, nullptr,
                                out + (long)bz * SEQ * DIM, nullptr,
                                DIM, SEQ, m0, n0, 1.f);
        }
        __syncthreads();   // protect s_t and smem reuse across iterations
    }
}

// ---------------------------------------------------------------------------
// Launch
// ---------------------------------------------------------------------------
extern "C" void kernel_launch(void* const* d_in, const int* in_sizes, int n_in,
                              void* d_out, int out_size)
{
    const float* x  = (const float*)d_in[0];
    const float* Wq = (const float*)d_in[1];
    const float* bq = (const float*)d_in[2];
    const float* Wk = (const float*)d_in[3];
    const float* bk = (const float*)d_in[4];
    const float* Wv = (const float*)d_in[5];
    const float* bv = (const float*)d_in[6];
    float* out = (float*)d_out;

    half *xh, *Wh;
    cudaGetSymbolAddress((void**)&xh, g_xh);
    cudaGetSymbolAddress((void**)&Wh, g_Wh);

    cudaFuncSetAttribute(mega, cudaFuncAttributeMaxDynamicSharedMemorySize, SMEM_MEGA);

    // resident-grid sizing (host-side queries; graph-capture safe)
    int dev = 0, nsm = 148, nb = 2;
    cudaGetDevice(&dev);
    cudaDeviceGetAttribute(&nsm, cudaDevAttrMultiProcessorCount, dev);
    cudaOccupancyMaxActiveBlocksPerMultiprocessor(&nb, mega, 256, SMEM_MEGA);
    if (nb < 1) nb = 1;
    int grid = nsm * nb;
    if (grid > T_TOTAL) grid = T_TOTAL;

    // 1) casts (also resets queue/sync counters)
    {
        dim3 g((MQ * DIM / 4 + 255) / 256, 4, 1);
        cast_all<<<g, 256>>>(x, Wq, Wk, Wv, xh, Wh);
    }

    // 2) everything else: persistent work-queue kernel
    mega<<<grid, 256, SMEM_MEGA>>>(bq, bk, bv, out);
}

// round 14
// speedup vs baseline: 1.0405x; 1.0209x over previous
#include <cuda_runtime.h>
#include <cuda_fp16.h>
#include <cstdint>

#define BATCH 4
#define SEQ   2048
#define DIM   1024
#define MQ    (BATCH * SEQ)   // 8192

// ---------------------------------------------------------------------------
// Persistent scratch (device globals — allocation-free per harness rules)
// ---------------------------------------------------------------------------
__device__ half  g_xh[(long)MQ * DIM];
__device__ half  g_Wh[3][(long)DIM * DIM];
__device__ half  g_QKV[3][(long)MQ * DIM];
__device__ float g_S[(long)BATCH * SEQ * SEQ];
__device__ half  g_Ph[(long)BATCH * SEQ * SEQ];

// work queue + fine-grained dependency counters
__device__ unsigned g_qnext;
__device__ unsigned g_cq[64];        // Q proj per m-block (8 n-tiles each)
__device__ unsigned g_ck[64];        // K proj per m-block
__device__ unsigned g_cv[BATCH];     // V proj per batch (128 tiles each)
__device__ unsigned g_csc[BATCH][16];// scores per (bz, m-block) (16 n-tiles)
__device__ unsigned g_csm[BATCH][16];// softmax per (bz, m-block) (16 items)

// Tile-queue layout (dependency order):
//   [0,512)      Q-proj   [512,1024) K-proj   [1024,1536) V-proj
//   [1536,2560)  scores   [2560,3584) softmax items(8 rows)  [3584,4096) AV
#define T_PROJ_END 1536
#define T_SC_END   2560
#define T_SM_END   3584
#define T_TOTAL    4096

// ---------------------------------------------------------------------------
// helpers
// ---------------------------------------------------------------------------
__device__ __forceinline__ uint32_t smem_u32(const void* p) {
    uint32_t a;
    asm("{ .reg .u64 t; cvta.to.shared.u64 t, %1; cvt.u32.u64 %0, t; }" : "=r"(a) : "l"(p));
    return a;
}
__device__ __forceinline__ void cp8(uint32_t dst, const void* src) {
    asm volatile("cp.async.ca.shared.global [%0], [%1], 8;" :: "r"(dst), "l"(src));
}
__device__ __forceinline__ void cp_commit() {
    asm volatile("cp.async.commit_group;" ::: "memory");
}
__device__ __forceinline__ void cp_wait1() {
    asm volatile("cp.async.wait_group 1;" ::: "memory");
}
__device__ __forceinline__ void cp_wait0() {
    asm volatile("cp.async.wait_group 0;" ::: "memory");
}
__device__ __forceinline__ void ldsm4(uint32_t r[4], uint32_t addr) {
    asm volatile("ldmatrix.sync.aligned.m8n8.x4.shared.b16 {%0,%1,%2,%3}, [%4];"
                 : "=r"(r[0]), "=r"(r[1]), "=r"(r[2]), "=r"(r[3]) : "r"(addr));
}
__device__ __forceinline__ void ldsm4t(uint32_t r[4], uint32_t addr) {
    asm volatile("ldmatrix.sync.aligned.m8n8.x4.trans.shared.b16 {%0,%1,%2,%3}, [%4];"
                 : "=r"(r[0]), "=r"(r[1]), "=r"(r[2]), "=r"(r[3]) : "r"(addr));
}
__device__ __forceinline__ void mma16816(float c[4], const uint32_t a[4],
                                         uint32_t b0, uint32_t b1) {
    asm volatile(
        "mma.sync.aligned.m16n8k16.row.col.f32.f16.f16.f32 "
        "{%0,%1,%2,%3}, {%4,%5,%6,%7}, {%8,%9}, {%0,%1,%2,%3};"
        : "+f"(c[0]), "+f"(c[1]), "+f"(c[2]), "+f"(c[3])
        : "r"(a[0]), "r"(a[1]), "r"(a[2]), "r"(a[3]), "r"(b0), "r"(b1));
}
__device__ __forceinline__ unsigned ld_acq(const unsigned* p) {
    unsigned v;
    asm volatile("ld.acquire.gpu.u32 %0, [%1];" : "=r"(v) : "l"(p) : "memory");
    return v;
}
__device__ __forceinline__ void spin_ge(const unsigned* p, unsigned tgt) {
    int it = 0;
    while (ld_acq(p) < tgt) {
        __nanosleep(64);
        if (++it > 8000000) break;   // safety valve: fail, don't hang
    }
}

// ---------------------------------------------------------------------------
// fp32 -> fp16 casts (y=0 -> x, y=1..3 -> W) + counter reset
// ---------------------------------------------------------------------------
__global__ void cast_all(const float* __restrict__ x,
                         const float* __restrict__ w0, const float* __restrict__ w1,
                         const float* __restrict__ w2,
                         half* __restrict__ xh, half* __restrict__ Wh)
{
    if (blockIdx.x == 0 && blockIdx.y == 0 && threadIdx.x < 256) {
        const int t = threadIdx.x;
        if (t == 0) g_qnext = 0;
        if (t < 64) { g_cq[t] = 0; g_ck[t] = 0; }
        if (t < BATCH) g_cv[t] = 0;
        if (t < BATCH * 16) {
            ((unsigned*)g_csc)[t] = 0;
            ((unsigned*)g_csm)[t] = 0;
        }
    }
    const int y = blockIdx.y;
    const float* s;
    half* d;
    int n4;
    if (y == 0) { s = x;  d = xh; n4 = MQ * DIM / 4; }
    else {
        s = (y == 1) ? w0 : (y == 2) ? w1 : w2;
        d = Wh + (long)(y - 1) * DIM * DIM;
        n4 = DIM * DIM / 4;
    }
    int i = blockIdx.x * blockDim.x + threadIdx.x;
    if (i >= n4) return;
    float4 v = ((const float4*)s)[i];
    half2 a; a.x = __float2half(v.x); a.y = __float2half(v.y);
    half2 b; b.x = __float2half(v.z); b.y = __float2half(v.w);
    ((half2*)d)[2 * i] = a;
    ((half2*)d)[2 * i + 1] = b;
}

// ---------------------------------------------------------------------------
// GEMM tile body (identical math to the 502us build)
// ---------------------------------------------------------------------------
#define LDA    40
#define LDBNN  136
#define STAGES 3

#define A_TILE_B   (128 * LDA * 2)          // 10240
#define BNT_TILE_B (128 * LDA * 2)          // 10240
#define BNN_TILE_B (32 * LDBNN * 2)         // 8704
#define SMEM_MEGA  (STAGES * (A_TILE_B + BNT_TILE_B))   // 61440

template <bool BKMAJOR, int MODE>
__device__ __forceinline__ void gemm_body(
    char* smem,
    const half* __restrict__ A, const half* __restrict__ B,
    const float* __restrict__ bias,
    float* __restrict__ Cf, half* __restrict__ Ch,
    int N, int K, int m0, int n0, float alpha)
{
    constexpr int B_TILE_B = BKMAJOR ? BNT_TILE_B : BNN_TILE_B;
    constexpr int OFF_B    = A_TILE_B;
    constexpr int STAGE_B  = A_TILE_B + B_TILE_B;

    const uint32_t sb = smem_u32(smem);
    const int tid = threadIdx.x;
    const int lane = tid & 31;
    const int wid = tid >> 5;
    const int wm = wid >> 2;
    const int wn = wid & 3;

    float c[4][4][4];
    #pragma unroll
    for (int i = 0; i < 4; i++)
        #pragma unroll
        for (int j = 0; j < 4; j++)
            #pragma unroll
            for (int r = 0; r < 4; r++) c[i][j][r] = 0.f;

    auto issue_stage = [&](int st, int k0) {
        const uint32_t s0 = sb + st * STAGE_B;
        #pragma unroll
        for (int i = 0; i < 4; i++) {
            const int q = i * 256 + tid;
            const int r = q >> 3, ch = q & 7;
            cp8(s0 + r * 80 + ch * 8, A + (long)(m0 + r) * K + k0 + ch * 4);
        }
        if (BKMAJOR) {
            #pragma unroll
            for (int i = 0; i < 4; i++) {
                const int q = i * 256 + tid;
                const int r = q >> 3, ch = q & 7;
                cp8(s0 + OFF_B + r * 80 + ch * 8, B + (long)(n0 + r) * K + k0 + ch * 4);
            }
        } else {
            #pragma unroll
            for (int i = 0; i < 4; i++) {
                const int q = i * 256 + tid;
                const int r = q >> 5, ch = q & 31;
                cp8(s0 + OFF_B + r * 272 + ch * 8, B + (long)(k0 + r) * N + n0 + ch * 4);
            }
        }
        cp_commit();
    };

    const int NIT = K >> 5;
    issue_stage(0, 0);
    issue_stage(1, 32);

    int st = 0;
    for (int it = 0; it < NIT; it++) {
        cp_wait1();
        __syncthreads();
        if (it + 2 < NIT) issue_stage((st + 2) % STAGES, (it + 2) * 32);

        const half* tA = (const half*)(smem + st * STAGE_B);
        const half* tB = (const half*)(smem + st * STAGE_B + OFF_B);

        #pragma unroll
        for (int ks = 0; ks < 2; ks++) {
            const int kk = ks * 16;
            uint32_t fa[4][4], fb[2][4];
            #pragma unroll
            for (int mf = 0; mf < 4; mf++) {
                const int row = wm * 64 + mf * 16 + (lane & 15);
                const int col = kk + (lane >> 4) * 8;
                ldsm4(fa[mf], smem_u32(&tA[row * LDA + col]));
            }
            if (BKMAJOR) {
                #pragma unroll
                for (int q = 0; q < 2; q++) {
                    const int row = wn * 32 + q * 16 + (lane & 15);
                    const int col = kk + (lane >> 4) * 8;
                    ldsm4(fb[q], smem_u32(&tB[row * LDA + col]));
                }
            } else {
                #pragma unroll
                for (int q = 0; q < 2; q++) {
                    const int row = kk + (lane >> 4) * 8 + (lane & 7);
                    const int col = wn * 32 + q * 16 + ((lane >> 3) & 1) * 8;
                    ldsm4t(fb[q], smem_u32(&tB[row * LDBNN + col]));
                }
            }
            #pragma unroll
            for (int mf = 0; mf < 4; mf++)
                #pragma unroll
                for (int nf = 0; nf < 4; nf++) {
                    const int q = nf >> 1, g = nf & 1;
                    mma16816(c[mf][nf], fa[mf], fb[q][g], fb[q][g + 2]);
                }
        }
        st = (st + 1) % STAGES;
    }
    cp_wait0();

    #pragma unroll
    for (int mf = 0; mf < 4; mf++) {
        const int m_lo = m0 + wm * 64 + mf * 16 + (lane >> 2);
        #pragma unroll
        for (int nf = 0; nf < 4; nf++) {
            const int n = n0 + wn * 32 + nf * 8 + (lane & 3) * 2;
            if (MODE == 1) {
                const float v0 = bias[n], v1 = bias[n + 1];
                __half2 h0; h0.x = __float2half(c[mf][nf][0] + v0);
                h0.y = __float2half(c[mf][nf][1] + v1);
                __half2 h1; h1.x = __float2half(c[mf][nf][2] + v0);
                h1.y = __float2half(c[mf][nf][3] + v1);
                *(__half2*)(Ch + (long)m_lo * N + n) = h0;
                *(__half2*)(Ch + (long)(m_lo + 8) * N + n) = h1;
            } else {
                float2 v0 = make_float2(c[mf][nf][0] * alpha, c[mf][nf][1] * alpha);
                float2 v1 = make_float2(c[mf][nf][2] * alpha, c[mf][nf][3] * alpha);
                *(float2*)(Cf + (long)m_lo * N + n) = v0;
                *(float2*)(Cf + (long)(m_lo + 8) * N + n) = v1;
            }
        }
    }
}

// ---------------------------------------------------------------------------
// One softmax row (vectorized)
// ---------------------------------------------------------------------------
__device__ __forceinline__ void softmax_row(char* smem, long row)
{
    float* red = (float*)smem;
    const float4* p4 = (const float4*)(g_S + row * SEQ);
    half* ph = g_Ph + row * SEQ;
    const int tid = threadIdx.x;

    float4 v0 = p4[tid];
    float4 v1 = p4[tid + 256];

    float m = fmaxf(fmaxf(fmaxf(v0.x, v0.y), fmaxf(v0.z, v0.w)),
                    fmaxf(fmaxf(v1.x, v1.y), fmaxf(v1.z, v1.w)));
    #pragma unroll
    for (int o = 16; o; o >>= 1) m = fmaxf(m, __shfl_xor_sync(0xffffffffu, m, o));
    if ((tid & 31) == 0) red[tid >> 5] = m;
    __syncthreads();
    m = red[0];
    #pragma unroll
    for (int w = 1; w < 8; w++) m = fmaxf(m, red[w]);
    __syncthreads();

    v0.x = __expf(v0.x - m); v0.y = __expf(v0.y - m);
    v0.z = __expf(v0.z - m); v0.w = __expf(v0.w - m);
    v1.x = __expf(v1.x - m); v1.y = __expf(v1.y - m);
    v1.z = __expf(v1.z - m); v1.w = __expf(v1.w - m);
    float s = (v0.x + v0.y) + (v0.z + v0.w) + (v1.x + v1.y) + (v1.z + v1.w);
    #pragma unroll
    for (int o = 16; o; o >>= 1) s += __shfl_xor_sync(0xffffffffu, s, o);
    if ((tid & 31) == 0) red[tid >> 5] = s;
    __syncthreads();
    s = 0.f;
    #pragma unroll
    for (int w = 0; w < 8; w++) s += red[w];
    const float inv = 1.f / s;

    __half2 a, b;
    uint2 pk;
    a.x = __float2half(v0.x * inv); a.y = __float2half(v0.y * inv);
    b.x = __float2half(v0.z * inv); b.y = __float2half(v0.w * inv);
    pk.x = *(uint32_t*)&a; pk.y = *(uint32_t*)&b;
    ((uint2*)ph)[tid] = pk;
    a.x = __float2half(v1.x * inv); a.y = __float2half(v1.y * inv);
    b.x = __float2half(v1.z * inv); b.y = __float2half(v1.w * inv);
    pk.x = *(uint32_t*)&a; pk.y = *(uint32_t*)&b;
    ((uint2*)ph)[tid + 256] = pk;
    __syncthreads();
}

// ---------------------------------------------------------------------------
// Persistent mega-kernel with fine-grained block-level dependency gates
// ---------------------------------------------------------------------------
__global__ __launch_bounds__(256, 2)
void mega(const float* __restrict__ bq, const float* __restrict__ bk,
          const float* __restrict__ bv, float* __restrict__ out)
{
    extern __shared__ char smem[];
    __shared__ unsigned s_t;
    const int tid = threadIdx.x;

    for (;;) {
        if (tid == 0) s_t = atomicAdd(&g_qnext, 1u);
        __syncthreads();
        const unsigned t = s_t;
        if (t >= T_TOTAL) return;

        if (t < T_PROJ_END) {
            // ---- projections: Q(0..511), K(512..1023), V(1024..1535) ----
            const int zsel = t >> 9;
            const int tt = t & 511;
            const int n0 = (tt & 7) * 128;
            const int mblk = tt >> 3;            // 0..63
            const int m0 = mblk * 128;
            const float* bias = (zsel == 0) ? bq : (zsel == 1) ? bk : bv;
            gemm_body<true, 1>(smem, g_xh, g_Wh[zsel], bias,
                               nullptr, g_QKV[zsel], DIM, DIM, m0, n0, 1.f);
            __threadfence();
            __syncthreads();
            if (tid == 0) {
                if (zsel == 0)      atomicAdd(&g_cq[mblk], 1u);
                else if (zsel == 1) atomicAdd(&g_ck[mblk], 1u);
                else                atomicAdd(&g_cv[mblk >> 4], 1u);
            }
        } else if (t < T_SC_END) {
            // ---- scores: gate on Q m-block + K n-block of this batch ----
            const int tt = t - T_PROJ_END;
            const int bz = tt >> 8;
            const int r = tt & 255;
            const int nblk = r & 15;
            const int mblk = r >> 4;
            if (tid == 0) {
                spin_ge(&g_cq[bz * 16 + mblk], 8u);
                spin_ge(&g_ck[bz * 16 + nblk], 8u);
            }
            __syncthreads();
            gemm_body<true, 2>(smem,
                               g_QKV[0] + (long)bz * SEQ * DIM,
                               g_QKV[1] + (long)bz * SEQ * DIM, nullptr,
                               g_S + (long)bz * SEQ * SEQ, nullptr,
                               SEQ, DIM, mblk * 128, nblk * 128, 0.03125f);
            __threadfence();
            __syncthreads();
            if (tid == 0) atomicAdd(&g_csc[bz][mblk], 1u);
        } else if (t < T_SM_END) {
            // ---- softmax: 8 rows; gate on scores row-block complete ----
            const long base = (long)(t - T_SC_END) * 8;   // global row
            const int bz = (int)(base >> 11);
            const int mblk = (int)(base >> 7) & 15;
            if (tid == 0) spin_ge(&g_csc[bz][mblk], 16u);
            __syncthreads();
            #pragma unroll 1
            for (int i = 0; i < 8; i++) softmax_row(smem, base + i);
            __threadfence();
            __syncthreads();
            if (tid == 0) atomicAdd(&g_csm[bz][mblk], 1u);
        } else {
            // ---- AV: gate on P m-block + all V of this batch ----
            const int tt = t - T_SM_END;
            const int bz = tt >> 7;
            const int r = tt & 127;
            const int n0 = (r & 7) * 128;
            const int mblk = r >> 3;
            if (tid == 0) {
                spin_ge(&g_csm[bz][mblk], 16u);
                spin_ge(&g_cv[bz], 128u);
            }
            __syncthreads();
            gemm_body<false, 2>(smem,
                                g_Ph + (long)bz * SEQ * SEQ,
                                g_QKV[2] + (long)bz * SEQ * DIM, nullptr,
                                out + (long)bz * SEQ * DIM, nullptr,
                                DIM, SEQ, mblk * 128, n0, 1.f);
        }
        __syncthreads();
    }
}

// ---------------------------------------------------------------------------
// Launch
// ---------------------------------------------------------------------------
extern "C" void kernel_launch(void* const* d_in, const int* in_sizes, int n_in,
                              void* d_out, int out_size)
{
    const float* x  = (const float*)d_in[0];
    const float* Wq = (const float*)d_in[1];
    const float* bq = (const float*)d_in[2];
    const float* Wk = (const float*)d_in[3];
    const float* bk = (const float*)d_in[4];
    const float* Wv = (const float*)d_in[5];
    const float* bv = (const float*)d_in[6];
    float* out = (float*)d_out;

    half *xh, *Wh;
    cudaGetSymbolAddress((void**)&xh, g_xh);
    cudaGetSymbolAddress((void**)&Wh, g_Wh);

    cudaFuncSetAttribute(mega, cudaFuncAttributeMaxDynamicSharedMemorySize, SMEM_MEGA);

    int dev = 0, nsm = 148, nb = 2;
    cudaGetDevice(&dev);
    cudaDeviceGetAttribute(&nsm, cudaDevAttrMultiProcessorCount, dev);
    cudaOccupancyMaxActiveBlocksPerMultiprocessor(&nb, mega, 256, SMEM_MEGA);
    if (nb < 1) nb = 1;
    int grid = nsm * nb;
    if (grid > T_TOTAL) grid = T_TOTAL;

    // 1) casts (also resets queue/sync counters)
    {
        dim3 g((MQ * DIM / 4 + 255) / 256, 4, 1);
        cast_all<<<g, 256>>>(x, Wq, Wk, Wv, xh, Wh);
    }

    // 2) everything else: persistent work-queue kernel
    mega<<<grid, 256, SMEM_MEGA>>>(bq, bk, bv, out);
}

// round 15
// speedup vs baseline: 1.0656x; 1.0241x over previous
#include <cuda_runtime.h>
#include <cuda_fp16.h>
#include <cstdint>

#define BATCH 4
#define SEQ   2048
#define DIM   1024
#define MQ    (BATCH * SEQ)   // 8192

// ---------------------------------------------------------------------------
// Persistent scratch (device globals — allocation-free per harness rules)
// ---------------------------------------------------------------------------
__device__ half  g_xh[(long)MQ * DIM];
__device__ half  g_Wh[3][(long)DIM * DIM];
__device__ half  g_QKV[3][(long)MQ * DIM];
__device__ float g_S[(long)BATCH * SEQ * SEQ];
__device__ half  g_Ph[(long)BATCH * SEQ * SEQ];

// work queue + fine-grained dependency counters (zero-init; self-reset at exit)
__device__ unsigned g_qnext;
__device__ unsigned g_exit;
__device__ unsigned g_cxc[64];        // x cast per 128-row m-block (4 tiles)
__device__ unsigned g_cwc[3][8];      // W cast per (zsel, n-block) (4 tiles)
__device__ unsigned g_cq[64];         // Q proj per m-block (8 n-tiles)
__device__ unsigned g_ck[64];         // K proj per m-block
__device__ unsigned g_cv[BATCH];      // V proj per batch (128 tiles)
__device__ unsigned g_csc[BATCH][16]; // scores per (bz, m-block) (16 n-tiles)
__device__ unsigned g_csm[BATCH][16]; // softmax per (bz, m-block) (16 items)

// Queue layout (dependency order):
//   [0,256)        x-cast (32 rows each)
//   [256,352)      W-cast (32 rows each; 32 per W)
//   [352,1888)     proj: Q(512) K(512) V(512)
//   [1888,2912)    scores
//   [2912,3936)    softmax items (8 rows each)
//   [3936,4448)    AV
#define T_XC_END   256
#define T_WC_END   352
#define T_PROJ_END 1888
#define T_SC_END   2912
#define T_SM_END   3936
#define T_TOTAL    4448

// ---------------------------------------------------------------------------
// helpers
// ---------------------------------------------------------------------------
__device__ __forceinline__ uint32_t smem_u32(const void* p) {
    uint32_t a;
    asm("{ .reg .u64 t; cvta.to.shared.u64 t, %1; cvt.u32.u64 %0, t; }" : "=r"(a) : "l"(p));
    return a;
}
__device__ __forceinline__ void cp8(uint32_t dst, const void* src) {
    asm volatile("cp.async.ca.shared.global [%0], [%1], 8;" :: "r"(dst), "l"(src));
}
__device__ __forceinline__ void cp_commit() {
    asm volatile("cp.async.commit_group;" ::: "memory");
}
__device__ __forceinline__ void cp_wait1() {
    asm volatile("cp.async.wait_group 1;" ::: "memory");
}
__device__ __forceinline__ void cp_wait0() {
    asm volatile("cp.async.wait_group 0;" ::: "memory");
}
__device__ __forceinline__ void ldsm4(uint32_t r[4], uint32_t addr) {
    asm volatile("ldmatrix.sync.aligned.m8n8.x4.shared.b16 {%0,%1,%2,%3}, [%4];"
                 : "=r"(r[0]), "=r"(r[1]), "=r"(r[2]), "=r"(r[3]) : "r"(addr));
}
__device__ __forceinline__ void ldsm4t(uint32_t r[4], uint32_t addr) {
    asm volatile("ldmatrix.sync.aligned.m8n8.x4.trans.shared.b16 {%0,%1,%2,%3}, [%4];"
                 : "=r"(r[0]), "=r"(r[1]), "=r"(r[2]), "=r"(r[3]) : "r"(addr));
}
__device__ __forceinline__ void mma16816(float c[4], const uint32_t a[4],
                                         uint32_t b0, uint32_t b1) {
    asm volatile(
        "mma.sync.aligned.m16n8k16.row.col.f32.f16.f16.f32 "
        "{%0,%1,%2,%3}, {%4,%5,%6,%7}, {%8,%9}, {%0,%1,%2,%3};"
        : "+f"(c[0]), "+f"(c[1]), "+f"(c[2]), "+f"(c[3])
        : "r"(a[0]), "r"(a[1]), "r"(a[2]), "r"(a[3]), "r"(b0), "r"(b1));
}
__device__ __forceinline__ unsigned ld_acq(const unsigned* p) {
    unsigned v;
    asm volatile("ld.acquire.gpu.u32 %0, [%1];" : "=r"(v) : "l"(p) : "memory");
    return v;
}
__device__ __forceinline__ void spin_ge(const unsigned* p, unsigned tgt) {
    int it = 0;
    while (ld_acq(p) < tgt) {
        __nanosleep(64);
        if (++it > 8000000) break;   // safety valve: fail, don't hang
    }
}

// ---------------------------------------------------------------------------
// cast tile: convert 32768 fp32 -> fp16 (32 rows of 1024)
// ---------------------------------------------------------------------------
__device__ __forceinline__ void cast_tile(const float* __restrict__ s,
                                          half* __restrict__ d, long base)
{
    const float4* s4 = (const float4*)(s) + base;
    half2* d2 = (half2*)(d) + base * 2;
    const int tid = threadIdx.x;
    #pragma unroll 4
    for (int it = 0; it < 32; it++) {
        const int i = it * 256 + tid;
        float4 v = s4[i];
        half2 a; a.x = __float2half(v.x); a.y = __float2half(v.y);
        half2 b; b.x = __float2half(v.z); b.y = __float2half(v.w);
        d2[2 * i] = a;
        d2[2 * i + 1] = b;
    }
}

// ---------------------------------------------------------------------------
// GEMM tile body (identical math to the 491us build)
// ---------------------------------------------------------------------------
#define LDA    40
#define LDBNN  136
#define STAGES 3

#define A_TILE_B   (128 * LDA * 2)          // 10240
#define BNT_TILE_B (128 * LDA * 2)          // 10240
#define BNN_TILE_B (32 * LDBNN * 2)         // 8704
#define SMEM_MEGA  (STAGES * (A_TILE_B + BNT_TILE_B))   // 61440

template <bool BKMAJOR, int MODE>
__device__ __forceinline__ void gemm_body(
    char* smem,
    const half* __restrict__ A, const half* __restrict__ B,
    const float* __restrict__ bias,
    float* __restrict__ Cf, half* __restrict__ Ch,
    int N, int K, int m0, int n0, float alpha)
{
    constexpr int B_TILE_B = BKMAJOR ? BNT_TILE_B : BNN_TILE_B;
    constexpr int OFF_B    = A_TILE_B;
    constexpr int STAGE_B  = A_TILE_B + B_TILE_B;

    const uint32_t sb = smem_u32(smem);
    const int tid = threadIdx.x;
    const int lane = tid & 31;
    const int wid = tid >> 5;
    const int wm = wid >> 2;
    const int wn = wid & 3;

    float c[4][4][4];
    #pragma unroll
    for (int i = 0; i < 4; i++)
        #pragma unroll
        for (int j = 0; j < 4; j++)
            #pragma unroll
            for (int r = 0; r < 4; r++) c[i][j][r] = 0.f;

    auto issue_stage = [&](int st, int k0) {
        const uint32_t s0 = sb + st * STAGE_B;
        #pragma unroll
        for (int i = 0; i < 4; i++) {
            const int q = i * 256 + tid;
            const int r = q >> 3, ch = q & 7;
            cp8(s0 + r * 80 + ch * 8, A + (long)(m0 + r) * K + k0 + ch * 4);
        }
        if (BKMAJOR) {
            #pragma unroll
            for (int i = 0; i < 4; i++) {
                const int q = i * 256 + tid;
                const int r = q >> 3, ch = q & 7;
                cp8(s0 + OFF_B + r * 80 + ch * 8, B + (long)(n0 + r) * K + k0 + ch * 4);
            }
        } else {
            #pragma unroll
            for (int i = 0; i < 4; i++) {
                const int q = i * 256 + tid;
                const int r = q >> 5, ch = q & 31;
                cp8(s0 + OFF_B + r * 272 + ch * 8, B + (long)(k0 + r) * N + n0 + ch * 4);
            }
        }
        cp_commit();
    };

    const int NIT = K >> 5;
    issue_stage(0, 0);
    issue_stage(1, 32);

    int st = 0;
    for (int it = 0; it < NIT; it++) {
        cp_wait1();
        __syncthreads();
        if (it + 2 < NIT) issue_stage((st + 2) % STAGES, (it + 2) * 32);

        const half* tA = (const half*)(smem + st * STAGE_B);
        const half* tB = (const half*)(smem + st * STAGE_B + OFF_B);

        #pragma unroll
        for (int ks = 0; ks < 2; ks++) {
            const int kk = ks * 16;
            uint32_t fa[4][4], fb[2][4];
            #pragma unroll
            for (int mf = 0; mf < 4; mf++) {
                const int row = wm * 64 + mf * 16 + (lane & 15);
                const int col = kk + (lane >> 4) * 8;
                ldsm4(fa[mf], smem_u32(&tA[row * LDA + col]));
            }
            if (BKMAJOR) {
                #pragma unroll
                for (int q = 0; q < 2; q++) {
                    const int row = wn * 32 + q * 16 + (lane & 15);
                    const int col = kk + (lane >> 4) * 8;
                    ldsm4(fb[q], smem_u32(&tB[row * LDA + col]));
                }
            } else {
                #pragma unroll
                for (int q = 0; q < 2; q++) {
                    const int row = kk + (lane >> 4) * 8 + (lane & 7);
                    const int col = wn * 32 + q * 16 + ((lane >> 3) & 1) * 8;
                    ldsm4t(fb[q], smem_u32(&tB[row * LDBNN + col]));
                }
            }
            #pragma unroll
            for (int mf = 0; mf < 4; mf++)
                #pragma unroll
                for (int nf = 0; nf < 4; nf++) {
                    const int q = nf >> 1, g = nf & 1;
                    mma16816(c[mf][nf], fa[mf], fb[q][g], fb[q][g + 2]);
                }
        }
        st = (st + 1) % STAGES;
    }
    cp_wait0();

    #pragma unroll
    for (int mf = 0; mf < 4; mf++) {
        const int m_lo = m0 + wm * 64 + mf * 16 + (lane >> 2);
        #pragma unroll
        for (int nf = 0; nf < 4; nf++) {
            const int n = n0 + wn * 32 + nf * 8 + (lane & 3) * 2;
            if (MODE == 1) {
                const float v0 = bias[n], v1 = bias[n + 1];
                __half2 h0; h0.x = __float2half(c[mf][nf][0] + v0);
                h0.y = __float2half(c[mf][nf][1] + v1);
                __half2 h1; h1.x = __float2half(c[mf][nf][2] + v0);
                h1.y = __float2half(c[mf][nf][3] + v1);
                *(__half2*)(Ch + (long)m_lo * N + n) = h0;
                *(__half2*)(Ch + (long)(m_lo + 8) * N + n) = h1;
            } else {
                float2 v0 = make_float2(c[mf][nf][0] * alpha, c[mf][nf][1] * alpha);
                float2 v1 = make_float2(c[mf][nf][2] * alpha, c[mf][nf][3] * alpha);
                *(float2*)(Cf + (long)m_lo * N + n) = v0;
                *(float2*)(Cf + (long)(m_lo + 8) * N + n) = v1;
            }
        }
    }
}

// ---------------------------------------------------------------------------
// One softmax row (vectorized)
// ---------------------------------------------------------------------------
__device__ __forceinline__ void softmax_row(char* smem, long row)
{
    float* red = (float*)smem;
    const float4* p4 = (const float4*)(g_S + row * SEQ);
    half* ph = g_Ph + row * SEQ;
    const int tid = threadIdx.x;

    float4 v0 = p4[tid];
    float4 v1 = p4[tid + 256];

    float m = fmaxf(fmaxf(fmaxf(v0.x, v0.y), fmaxf(v0.z, v0.w)),
                    fmaxf(fmaxf(v1.x, v1.y), fmaxf(v1.z, v1.w)));
    #pragma unroll
    for (int o = 16; o; o >>= 1) m = fmaxf(m, __shfl_xor_sync(0xffffffffu, m, o));
    if ((tid & 31) == 0) red[tid >> 5] = m;
    __syncthreads();
    m = red[0];
    #pragma unroll
    for (int w = 1; w < 8; w++) m = fmaxf(m, red[w]);
    __syncthreads();

    v0.x = __expf(v0.x - m); v0.y = __expf(v0.y - m);
    v0.z = __expf(v0.z - m); v0.w = __expf(v0.w - m);
    v1.x = __expf(v1.x - m); v1.y = __expf(v1.y - m);
    v1.z = __expf(v1.z - m); v1.w = __expf(v1.w - m);
    float s = (v0.x + v0.y) + (v0.z + v0.w) + (v1.x + v1.y) + (v1.z + v1.w);
    #pragma unroll
    for (int o = 16; o; o >>= 1) s += __shfl_xor_sync(0xffffffffu, s, o);
    if ((tid & 31) == 0) red[tid >> 5] = s;
    __syncthreads();
    s = 0.f;
    #pragma unroll
    for (int w = 0; w < 8; w++) s += red[w];
    const float inv = 1.f / s;

    __half2 a, b;
    uint2 pk;
    a.x = __float2half(v0.x * inv); a.y = __float2half(v0.y * inv);
    b.x = __float2half(v0.z * inv); b.y = __float2half(v0.w * inv);
    pk.x = *(uint32_t*)&a; pk.y = *(uint32_t*)&b;
    ((uint2*)ph)[tid] = pk;
    a.x = __float2half(v1.x * inv); a.y = __float2half(v1.y * inv);
    b.x = __float2half(v1.z * inv); b.y = __float2half(v1.w * inv);
    pk.x = *(uint32_t*)&a; pk.y = *(uint32_t*)&b;
    ((uint2*)ph)[tid + 256] = pk;
    __syncthreads();
}

// ---------------------------------------------------------------------------
// Persistent mega-kernel: casts + GEMMs + softmax in one work queue.
// Counters are zero-init globals; last exiting CTA resets them (replay-safe).
// ---------------------------------------------------------------------------
__global__ __launch_bounds__(256, 2)
void mega(const float* __restrict__ x,
          const float* __restrict__ Wq, const float* __restrict__ Wk,
          const float* __restrict__ Wv,
          const float* __restrict__ bq, const float* __restrict__ bk,
          const float* __restrict__ bv, float* __restrict__ out)
{
    extern __shared__ char smem[];
    __shared__ unsigned s_t;
    const int tid = threadIdx.x;

    for (;;) {
        if (tid == 0) s_t = atomicAdd(&g_qnext, 1u);
        __syncthreads();
        const unsigned t = s_t;
        if (t >= T_TOTAL) break;

        if (t < T_XC_END) {
            // ---- x cast: 32 rows ----
            cast_tile(x, g_xh, (long)t * 8192);
            __threadfence();
            __syncthreads();
            if (tid == 0) atomicAdd(&g_cxc[t >> 2], 1u);
        } else if (t < T_WC_END) {
            // ---- W cast: 32 rows of W[zsel] ----
            const int j = t - T_XC_END;
            const int zsel = j >> 5;
            const int sub = j & 31;
            const float* W = (zsel == 0) ? Wq : (zsel == 1) ? Wk : Wv;
            cast_tile(W, g_Wh[zsel], (long)sub * 8192);
            __threadfence();
            __syncthreads();
            if (tid == 0) atomicAdd(&g_cwc[zsel][sub >> 2], 1u);
        } else if (t < T_PROJ_END) {
            // ---- projections: Q, K, V; gate on cast blocks ----
            const int tt = t - T_WC_END;
            const int zsel = tt >> 9;
            const int r = tt & 511;
            const int nblk = r & 7;
            const int mblk = r >> 3;
            if (tid == 0) {
                spin_ge(&g_cxc[mblk], 4u);
                spin_ge(&g_cwc[zsel][nblk], 4u);
            }
            __syncthreads();
            const float* bias = (zsel == 0) ? bq : (zsel == 1) ? bk : bv;
            gemm_body<true, 1>(smem, g_xh, g_Wh[zsel], bias,
                               nullptr, g_QKV[zsel], DIM, DIM,
                               mblk * 128, nblk * 128, 1.f);
            __threadfence();
            __syncthreads();
            if (tid == 0) {
                if (zsel == 0)      atomicAdd(&g_cq[mblk], 1u);
                else if (zsel == 1) atomicAdd(&g_ck[mblk], 1u);
                else                atomicAdd(&g_cv[mblk >> 4], 1u);
            }
        } else if (t < T_SC_END) {
            // ---- scores: gate on Q m-block + K n-block of this batch ----
            const int tt = t - T_PROJ_END;
            const int bz = tt >> 8;
            const int r = tt & 255;
            const int nblk = r & 15;
            const int mblk = r >> 4;
            if (tid == 0) {
                spin_ge(&g_cq[bz * 16 + mblk], 8u);
                spin_ge(&g_ck[bz * 16 + nblk], 8u);
            }
            __syncthreads();
            gemm_body<true, 2>(smem,
                               g_QKV[0] + (long)bz * SEQ * DIM,
                               g_QKV[1] + (long)bz * SEQ * DIM, nullptr,
                               g_S + (long)bz * SEQ * SEQ, nullptr,
                               SEQ, DIM, mblk * 128, nblk * 128, 0.03125f);
            __threadfence();
            __syncthreads();
            if (tid == 0) atomicAdd(&g_csc[bz][mblk], 1u);
        } else if (t < T_SM_END) {
            // ---- softmax: 8 rows; gate on scores row-block complete ----
            const long base = (long)(t - T_SC_END) * 8;
            const int bz = (int)(base >> 11);
            const int mblk = (int)(base >> 7) & 15;
            if (tid == 0) spin_ge(&g_csc[bz][mblk], 16u);
            __syncthreads();
            #pragma unroll 1
            for (int i = 0; i < 8; i++) softmax_row(smem, base + i);
            __threadfence();
            __syncthreads();
            if (tid == 0) atomicAdd(&g_csm[bz][mblk], 1u);
        } else {
            // ---- AV: gate on P m-block + all V of this batch ----
            const int tt = t - T_SM_END;
            const int bz = tt >> 7;
            const int r = tt & 127;
            const int n0 = (r & 7) * 128;
            const int mblk = r >> 3;
            if (tid == 0) {
                spin_ge(&g_csm[bz][mblk], 16u);
                spin_ge(&g_cv[bz], 128u);
            }
            __syncthreads();
            gemm_body<false, 2>(smem,
                                g_Ph + (long)bz * SEQ * SEQ,
                                g_QKV[2] + (long)bz * SEQ * DIM, nullptr,
                                out + (long)bz * SEQ * DIM, nullptr,
                                DIM, SEQ, mblk * 128, n0, 1.f);
        }
        __syncthreads();
    }

    // ---- exit: last CTA out resets all counters (replay-safe) ----
    if (tid == 0) {
        const unsigned e = atomicAdd(&g_exit, 1u);
        if (e == gridDim.x - 1) {
            g_qnext = 0; g_exit = 0;
            #pragma unroll 1
            for (int i = 0; i < 64; i++) { g_cxc[i] = 0; g_cq[i] = 0; g_ck[i] = 0; }
            #pragma unroll 1
            for (int i = 0; i < 24; i++) ((unsigned*)g_cwc)[i] = 0;
            #pragma unroll 1
            for (int i = 0; i < BATCH; i++) g_cv[i] = 0;
            #pragma unroll 1
            for (int i = 0; i < 64; i++) {
                ((unsigned*)g_csc)[i] = 0;
                ((unsigned*)g_csm)[i] = 0;
            }
            __threadfence();
        }
    }
}

// ---------------------------------------------------------------------------
// Launch
// ---------------------------------------------------------------------------
extern "C" void kernel_launch(void* const* d_in, const int* in_sizes, int n_in,
                              void* d_out, int out_size)
{
    const float* x  = (const float*)d_in[0];
    const float* Wq = (const float*)d_in[1];
    const float* bq = (const float*)d_in[2];
    const float* Wk = (const float*)d_in[3];
    const float* bk = (const float*)d_in[4];
    const float* Wv = (const float*)d_in[5];
    const float* bv = (const float*)d_in[6];
    float* out = (float*)d_out;

    cudaFuncSetAttribute(mega, cudaFuncAttributeMaxDynamicSharedMemorySize, SMEM_MEGA);

    int dev = 0, nsm = 148, nb = 2;
    cudaGetDevice(&dev);
    cudaDeviceGetAttribute(&nsm, cudaDevAttrMultiProcessorCount, dev);
    cudaOccupancyMaxActiveBlocksPerMultiprocessor(&nb, mega, 256, SMEM_MEGA);
    if (nb < 1) nb = 1;
    int grid = nsm * nb;
    if (grid > T_TOTAL) grid = T_TOTAL;

    mega<<<grid, 256, SMEM_MEGA>>>(x, Wq, Wk, Wv, bq, bk, bv, out);
}

// round 16
// speedup vs baseline: 1.1017x; 1.0338x over previous
#include <cuda_runtime.h>
#include <cuda_fp16.h>
#include <cstdint>
#include <math_constants.h>

#define BATCH 4
#define SEQ   2048
#define DIM   1024
#define MQ    (BATCH * SEQ)   // 8192

// ---------------------------------------------------------------------------
// Persistent scratch (device globals — allocation-free per harness rules)
// ---------------------------------------------------------------------------
__device__ half  g_xh[(long)MQ * DIM];
__device__ half  g_Wh[3][(long)DIM * DIM];
__device__ half  g_QKV[3][(long)MQ * DIM];
__device__ float g_S[(long)BATCH * SEQ * SEQ];
__device__ half  g_Ph[(long)BATCH * SEQ * SEQ];

// work queue + fine-grained dependency counters (zero-init; self-reset at exit)
__device__ unsigned g_qnext;
__device__ unsigned g_exit;
__device__ unsigned g_cxc[64];        // x cast per 128-row m-block (4 tiles)
__device__ unsigned g_cwc[3][8];      // W cast per (zsel, n-block) (4 tiles)
__device__ unsigned g_cq[64];         // Q proj per m-block (8 n-tiles)
__device__ unsigned g_ck[64];         // K proj per m-block
__device__ unsigned g_cv[BATCH];      // V proj per batch (128 tiles)
__device__ unsigned g_csc[BATCH][16]; // scores per (bz, m-block) (16 n-tiles)
__device__ unsigned g_csm[BATCH][16]; // softmax per (bz, m-block) (16 items)

// Queue layout (dependency order):
//   [0,256)        x-cast (32 rows each)
//   [256,352)      W-cast (32 rows each; 32 per W)
//   [352,1888)     proj: Q(512) K(512) V(512)
//   [1888,2912)    scores
//   [2912,3936)    softmax items (8 rows each, warp-per-row)
//   [3936,4448)    AV
#define T_XC_END   256
#define T_WC_END   352
#define T_PROJ_END 1888
#define T_SC_END   2912
#define T_SM_END   3936
#define T_TOTAL    4448

// ---------------------------------------------------------------------------
// helpers
// ---------------------------------------------------------------------------
__device__ __forceinline__ uint32_t smem_u32(const void* p) {
    uint32_t a;
    asm("{ .reg .u64 t; cvta.to.shared.u64 t, %1; cvt.u32.u64 %0, t; }" : "=r"(a) : "l"(p));
    return a;
}
__device__ __forceinline__ void cp8(uint32_t dst, const void* src) {
    asm volatile("cp.async.ca.shared.global [%0], [%1], 8;" :: "r"(dst), "l"(src));
}
__device__ __forceinline__ void cp_commit() {
    asm volatile("cp.async.commit_group;" ::: "memory");
}
__device__ __forceinline__ void cp_wait1() {
    asm volatile("cp.async.wait_group 1;" ::: "memory");
}
__device__ __forceinline__ void cp_wait0() {
    asm volatile("cp.async.wait_group 0;" ::: "memory");
}
__device__ __forceinline__ void ldsm4(uint32_t r[4], uint32_t addr) {
    asm volatile("ldmatrix.sync.aligned.m8n8.x4.shared.b16 {%0,%1,%2,%3}, [%4];"
                 : "=r"(r[0]), "=r"(r[1]), "=r"(r[2]), "=r"(r[3]) : "r"(addr));
}
__device__ __forceinline__ void ldsm4t(uint32_t r[4], uint32_t addr) {
    asm volatile("ldmatrix.sync.aligned.m8n8.x4.trans.shared.b16 {%0,%1,%2,%3}, [%4];"
                 : "=r"(r[0]), "=r"(r[1]), "=r"(r[2]), "=r"(r[3]) : "r"(addr));
}
__device__ __forceinline__ void mma16816(float c[4], const uint32_t a[4],
                                         uint32_t b0, uint32_t b1) {
    asm volatile(
        "mma.sync.aligned.m16n8k16.row.col.f32.f16.f16.f32 "
        "{%0,%1,%2,%3}, {%4,%5,%6,%7}, {%8,%9}, {%0,%1,%2,%3};"
        : "+f"(c[0]), "+f"(c[1]), "+f"(c[2]), "+f"(c[3])
        : "r"(a[0]), "r"(a[1]), "r"(a[2]), "r"(a[3]), "r"(b0), "r"(b1));
}
__device__ __forceinline__ unsigned ld_acq(const unsigned* p) {
    unsigned v;
    asm volatile("ld.acquire.gpu.u32 %0, [%1];" : "=r"(v) : "l"(p) : "memory");
    return v;
}
__device__ __forceinline__ void spin_ge(const unsigned* p, unsigned tgt) {
    int it = 0;
    while (ld_acq(p) < tgt) {
        __nanosleep(64);
        if (++it > 8000000) break;   // safety valve: fail, don't hang
    }
}

// ---------------------------------------------------------------------------
// cast tile: convert 32768 fp32 -> fp16 (32 rows of 1024)
// ---------------------------------------------------------------------------
__device__ __forceinline__ void cast_tile(const float* __restrict__ s,
                                          half* __restrict__ d, long base)
{
    const float4* s4 = (const float4*)(s) + base;
    half2* d2 = (half2*)(d) + base * 2;
    const int tid = threadIdx.x;
    #pragma unroll 4
    for (int it = 0; it < 32; it++) {
        const int i = it * 256 + tid;
        float4 v = s4[i];
        half2 a; a.x = __float2half(v.x); a.y = __float2half(v.y);
        half2 b; b.x = __float2half(v.z); b.y = __float2half(v.w);
        d2[2 * i] = a;
        d2[2 * i + 1] = b;
    }
}

// ---------------------------------------------------------------------------
// GEMM tile body (identical math to the 480us build)
// ---------------------------------------------------------------------------
#define LDA    40
#define LDBNN  136
#define STAGES 3

#define A_TILE_B   (128 * LDA * 2)          // 10240
#define BNT_TILE_B (128 * LDA * 2)          // 10240
#define BNN_TILE_B (32 * LDBNN * 2)         // 8704
#define SMEM_MEGA  (STAGES * (A_TILE_B + BNT_TILE_B))   // 61440

template <bool BKMAJOR, int MODE>
__device__ __forceinline__ void gemm_body(
    char* smem,
    const half* __restrict__ A, const half* __restrict__ B,
    const float* __restrict__ bias,
    float* __restrict__ Cf, half* __restrict__ Ch,
    int N, int K, int m0, int n0, float alpha)
{
    constexpr int B_TILE_B = BKMAJOR ? BNT_TILE_B : BNN_TILE_B;
    constexpr int OFF_B    = A_TILE_B;
    constexpr int STAGE_B  = A_TILE_B + B_TILE_B;

    const uint32_t sb = smem_u32(smem);
    const int tid = threadIdx.x;
    const int lane = tid & 31;
    const int wid = tid >> 5;
    const int wm = wid >> 2;
    const int wn = wid & 3;

    float c[4][4][4];
    #pragma unroll
    for (int i = 0; i < 4; i++)
        #pragma unroll
        for (int j = 0; j < 4; j++)
            #pragma unroll
            for (int r = 0; r < 4; r++) c[i][j][r] = 0.f;

    auto issue_stage = [&](int st, int k0) {
        const uint32_t s0 = sb + st * STAGE_B;
        #pragma unroll
        for (int i = 0; i < 4; i++) {
            const int q = i * 256 + tid;
            const int r = q >> 3, ch = q & 7;
            cp8(s0 + r * 80 + ch * 8, A + (long)(m0 + r) * K + k0 + ch * 4);
        }
        if (BKMAJOR) {
            #pragma unroll
            for (int i = 0; i < 4; i++) {
                const int q = i * 256 + tid;
                const int r = q >> 3, ch = q & 7;
                cp8(s0 + OFF_B + r * 80 + ch * 8, B + (long)(n0 + r) * K + k0 + ch * 4);
            }
        } else {
            #pragma unroll
            for (int i = 0; i < 4; i++) {
                const int q = i * 256 + tid;
                const int r = q >> 5, ch = q & 31;
                cp8(s0 + OFF_B + r * 272 + ch * 8, B + (long)(k0 + r) * N + n0 + ch * 4);
            }
        }
        cp_commit();
    };

    const int NIT = K >> 5;
    issue_stage(0, 0);
    issue_stage(1, 32);

    int st = 0;
    for (int it = 0; it < NIT; it++) {
        cp_wait1();
        __syncthreads();
        if (it + 2 < NIT) issue_stage((st + 2) % STAGES, (it + 2) * 32);

        const half* tA = (const half*)(smem + st * STAGE_B);
        const half* tB = (const half*)(smem + st * STAGE_B + OFF_B);

        #pragma unroll
        for (int ks = 0; ks < 2; ks++) {
            const int kk = ks * 16;
            uint32_t fa[4][4], fb[2][4];
            #pragma unroll
            for (int mf = 0; mf < 4; mf++) {
                const int row = wm * 64 + mf * 16 + (lane & 15);
                const int col = kk + (lane >> 4) * 8;
                ldsm4(fa[mf], smem_u32(&tA[row * LDA + col]));
            }
            if (BKMAJOR) {
                #pragma unroll
                for (int q = 0; q < 2; q++) {
                    const int row = wn * 32 + q * 16 + (lane & 15);
                    const int col = kk + (lane >> 4) * 8;
                    ldsm4(fb[q], smem_u32(&tB[row * LDA + col]));
                }
            } else {
                #pragma unroll
                for (int q = 0; q < 2; q++) {
                    const int row = kk + (lane >> 4) * 8 + (lane & 7);
                    const int col = wn * 32 + q * 16 + ((lane >> 3) & 1) * 8;
                    ldsm4t(fb[q], smem_u32(&tB[row * LDBNN + col]));
                }
            }
            #pragma unroll
            for (int mf = 0; mf < 4; mf++)
                #pragma unroll
                for (int nf = 0; nf < 4; nf++) {
                    const int q = nf >> 1, g = nf & 1;
                    mma16816(c[mf][nf], fa[mf], fb[q][g], fb[q][g + 2]);
                }
        }
        st = (st + 1) % STAGES;
    }
    cp_wait0();

    #pragma unroll
    for (int mf = 0; mf < 4; mf++) {
        const int m_lo = m0 + wm * 64 + mf * 16 + (lane >> 2);
        #pragma unroll
        for (int nf = 0; nf < 4; nf++) {
            const int n = n0 + wn * 32 + nf * 8 + (lane & 3) * 2;
            if (MODE == 1) {
                const float v0 = bias[n], v1 = bias[n + 1];
                __half2 h0; h0.x = __float2half(c[mf][nf][0] + v0);
                h0.y = __float2half(c[mf][nf][1] + v1);
                __half2 h1; h1.x = __float2half(c[mf][nf][2] + v0);
                h1.y = __float2half(c[mf][nf][3] + v1);
                *(__half2*)(Ch + (long)m_lo * N + n) = h0;
                *(__half2*)(Ch + (long)(m_lo + 8) * N + n) = h1;
            } else {
                float2 v0 = make_float2(c[mf][nf][0] * alpha, c[mf][nf][1] * alpha);
                float2 v1 = make_float2(c[mf][nf][2] * alpha, c[mf][nf][3] * alpha);
                *(float2*)(Cf + (long)m_lo * N + n) = v0;
                *(float2*)(Cf + (long)(m_lo + 8) * N + n) = v1;
            }
        }
    }
}

// ---------------------------------------------------------------------------
// Softmax item: 8 rows, warp w handles row base+w autonomously.
// Two-pass: online max/rescaled-sum over the row, shuffle-combine, then
// reload (L2-hot), normalize, store fp16. No block syncs.
// ---------------------------------------------------------------------------
__device__ __forceinline__ void softmax_item8(long base)
{
    const int lane = threadIdx.x & 31;
    const int w = threadIdx.x >> 5;            // 0..7
    const long row = base + w;
    const float4* p4 = (const float4*)(g_S + row * SEQ);
    half* ph = g_Ph + row * SEQ;

    // pass 1: online max + rescaled sum (16 float4 per lane, stride 32)
    float m = -CUDART_INF_F, s = 0.f;
    #pragma unroll
    for (int i = 0; i < 16; i++) {
        float4 v = p4[i * 32 + lane];
        float vm = fmaxf(fmaxf(v.x, v.y), fmaxf(v.z, v.w));
        float nm = fmaxf(m, vm);
        s = s * __expf(m - nm)
          + __expf(v.x - nm) + __expf(v.y - nm)
          + __expf(v.z - nm) + __expf(v.w - nm);
        m = nm;
    }
    // combine across lanes
    #pragma unroll
    for (int o = 16; o; o >>= 1) {
        float om = __shfl_xor_sync(0xffffffffu, m, o);
        float os = __shfl_xor_sync(0xffffffffu, s, o);
        float nm = fmaxf(m, om);
        s = s * __expf(m - nm) + os * __expf(om - nm);
        m = nm;
    }
    const float inv = 1.f / s;

    // pass 2: reload (L2-hot), normalize, store packed fp16
    #pragma unroll
    for (int i = 0; i < 16; i++) {
        float4 v = p4[i * 32 + lane];
        __half2 a, b;
        a.x = __float2half(__expf(v.x - m) * inv);
        a.y = __float2half(__expf(v.y - m) * inv);
        b.x = __float2half(__expf(v.z - m) * inv);
        b.y = __float2half(__expf(v.w - m) * inv);
        uint2 pk;
        pk.x = *(uint32_t*)&a;
        pk.y = *(uint32_t*)&b;
        ((uint2*)ph)[i * 32 + lane] = pk;
    }
}

// ---------------------------------------------------------------------------
// Persistent mega-kernel: casts + GEMMs + softmax in one work queue.
// Counters are zero-init globals; last exiting CTA resets them (replay-safe).
// ---------------------------------------------------------------------------
__global__ __launch_bounds__(256, 2)
void mega(const float* __restrict__ x,
          const float* __restrict__ Wq, const float* __restrict__ Wk,
          const float* __restrict__ Wv,
          const float* __restrict__ bq, const float* __restrict__ bk,
          const float* __restrict__ bv, float* __restrict__ out)
{
    extern __shared__ char smem[];
    __shared__ unsigned s_t;
    const int tid = threadIdx.x;

    for (;;) {
        if (tid == 0) s_t = atomicAdd(&g_qnext, 1u);
        __syncthreads();
        const unsigned t = s_t;
        if (t >= T_TOTAL) break;

        if (t < T_XC_END) {
            // ---- x cast: 32 rows ----
            cast_tile(x, g_xh, (long)t * 8192);
            __threadfence();
            __syncthreads();
            if (tid == 0) atomicAdd(&g_cxc[t >> 2], 1u);
        } else if (t < T_WC_END) {
            // ---- W cast: 32 rows of W[zsel] ----
            const int j = t - T_XC_END;
            const int zsel = j >> 5;
            const int sub = j & 31;
            const float* W = (zsel == 0) ? Wq : (zsel == 1) ? Wk : Wv;
            cast_tile(W, g_Wh[zsel], (long)sub * 8192);
            __threadfence();
            __syncthreads();
            if (tid == 0) atomicAdd(&g_cwc[zsel][sub >> 2], 1u);
        } else if (t < T_PROJ_END) {
            // ---- projections: Q, K, V; gate on cast blocks ----
            const int tt = t - T_WC_END;
            const int zsel = tt >> 9;
            const int r = tt & 511;
            const int nblk = r & 7;
            const int mblk = r >> 3;
            if (tid == 0) {
                spin_ge(&g_cxc[mblk], 4u);
                spin_ge(&g_cwc[zsel][nblk], 4u);
            }
            __syncthreads();
            const float* bias = (zsel == 0) ? bq : (zsel == 1) ? bk : bv;
            gemm_body<true, 1>(smem, g_xh, g_Wh[zsel], bias,
                               nullptr, g_QKV[zsel], DIM, DIM,
                               mblk * 128, nblk * 128, 1.f);
            __threadfence();
            __syncthreads();
            if (tid == 0) {
                if (zsel == 0)      atomicAdd(&g_cq[mblk], 1u);
                else if (zsel == 1) atomicAdd(&g_ck[mblk], 1u);
                else                atomicAdd(&g_cv[mblk >> 4], 1u);
            }
        } else if (t < T_SC_END) {
            // ---- scores: gate on Q m-block + K n-block of this batch ----
            const int tt = t - T_PROJ_END;
            const int bz = tt >> 8;
            const int r = tt & 255;
            const int nblk = r & 15;
            const int mblk = r >> 4;
            if (tid == 0) {
                spin_ge(&g_cq[bz * 16 + mblk], 8u);
                spin_ge(&g_ck[bz * 16 + nblk], 8u);
            }
            __syncthreads();
            gemm_body<true, 2>(smem,
                               g_QKV[0] + (long)bz * SEQ * DIM,
                               g_QKV[1] + (long)bz * SEQ * DIM, nullptr,
                               g_S + (long)bz * SEQ * SEQ, nullptr,
                               SEQ, DIM, mblk * 128, nblk * 128, 0.03125f);
            __threadfence();
            __syncthreads();
            if (tid == 0) atomicAdd(&g_csc[bz][mblk], 1u);
        } else if (t < T_SM_END) {
            // ---- softmax: 8 rows, warp-per-row; gate on scores block ----
            const long base = (long)(t - T_SC_END) * 8;
            const int bz = (int)(base >> 11);
            const int mblk = (int)(base >> 7) & 15;
            if (tid == 0) spin_ge(&g_csc[bz][mblk], 16u);
            __syncthreads();
            softmax_item8(base);
            __threadfence();
            __syncthreads();
            if (tid == 0) atomicAdd(&g_csm[bz][mblk], 1u);
        } else {
            // ---- AV: gate on P m-block + all V of this batch ----
            const int tt = t - T_SM_END;
            const int bz = tt >> 7;
            const int r = tt & 127;
            const int n0 = (r & 7) * 128;
            const int mblk = r >> 3;
            if (tid == 0) {
                spin_ge(&g_csm[bz][mblk], 16u);
                spin_ge(&g_cv[bz], 128u);
            }
            __syncthreads();
            gemm_body<false, 2>(smem,
                                g_Ph + (long)bz * SEQ * SEQ,
                                g_QKV[2] + (long)bz * SEQ * DIM, nullptr,
                                out + (long)bz * SEQ * DIM, nullptr,
                                DIM, SEQ, mblk * 128, n0, 1.f);
        }
        __syncthreads();
    }

    // ---- exit: last CTA out resets all counters (replay-safe) ----
    if (tid == 0) {
        const unsigned e = atomicAdd(&g_exit, 1u);
        if (e == gridDim.x - 1) {
            g_qnext = 0; g_exit = 0;
            #pragma unroll 1
            for (int i = 0; i < 64; i++) { g_cxc[i] = 0; g_cq[i] = 0; g_ck[i] = 0; }
            #pragma unroll 1
            for (int i = 0; i < 24; i++) ((unsigned*)g_cwc)[i] = 0;
            #pragma unroll 1
            for (int i = 0; i < BATCH; i++) g_cv[i] = 0;
            #pragma unroll 1
            for (int i = 0; i < 64; i++) {
                ((unsigned*)g_csc)[i] = 0;
                ((unsigned*)g_csm)[i] = 0;
            }
            __threadfence();
        }
    }
}

// ---------------------------------------------------------------------------
// Launch
// ---------------------------------------------------------------------------
extern "C" void kernel_launch(void* const* d_in, const int* in_sizes, int n_in,
                              void* d_out, int out_size)
{
    const float* x  = (const float*)d_in[0];
    const float* Wq = (const float*)d_in[1];
    const float* bq = (const float*)d_in[2];
    const float* Wk = (const float*)d_in[3];
    const float* bk = (const float*)d_in[4];
    const float* Wv = (const float*)d_in[5];
    const float* bv = (const float*)d_in[6];
    float* out = (float*)d_out;

    cudaFuncSetAttribute(mega, cudaFuncAttributeMaxDynamicSharedMemorySize, SMEM_MEGA);

    int dev = 0, nsm = 148, nb = 2;
    cudaGetDevice(&dev);
    cudaDeviceGetAttribute(&nsm, cudaDevAttrMultiProcessorCount, dev);
    cudaOccupancyMaxActiveBlocksPerMultiprocessor(&nb, mega, 256, SMEM_MEGA);
    if (nb < 1) nb = 1;
    int grid = nsm * nb;
    if (grid > T_TOTAL) grid = T_TOTAL;

    mega<<<grid, 256, SMEM_MEGA>>>(x, Wq, Wk, Wv, bq, bk, bv, out);
}